// round 1
// baseline (speedup 1.0000x reference)
#include <cuda_runtime.h>

#define B_SZ 8
#define NPTS 16384
#define MSRC 1024
#define C1   128
#define C2   256
#define CIN  384
#define CO   256
#define BN_EPS 1e-5f

// Scratch (allocation-free): concatenated features X (B,384,N) and layer-0 output Y0 (B,256,N)
__device__ float g_X [(size_t)B_SZ * CIN * NPTS];   // ~201 MB
__device__ float g_Y0[(size_t)B_SZ * CO  * NPTS];   // ~134 MB

// ---------------------------------------------------------------------------
// Kernel 1: fused three_nn + inverse-distance interpolation + concat
// Grid: (NPTS/128, B), Block: 128 threads. Each thread owns one target point.
// ---------------------------------------------------------------------------
__global__ void __launch_bounds__(128)
interp_concat_kernel(const float* __restrict__ target,   // (B, N, 3)
                     const float* __restrict__ source,   // (B, M, 3)
                     const float* __restrict__ tfeat,    // (B, C1, N)
                     const float* __restrict__ sfeat,    // (B, C2, M)
                     float* __restrict__ X)              // (B, CIN, N)
{
    const int b  = blockIdx.y;
    const int i0 = blockIdx.x * 128;
    const int t  = threadIdx.x;

    __shared__ float sx[MSRC], sy[MSRC], sz[MSRC];
    __shared__ int   s_idx[3][128];
    __shared__ float s_w [3][128];

    // Stage source positions for this batch (12 KB)
    const float* src = source + (size_t)b * MSRC * 3;
    for (int j = t; j < MSRC; j += 128) {
        sx[j] = src[j * 3 + 0];
        sy[j] = src[j * 3 + 1];
        sz[j] = src[j * 3 + 2];
    }
    __syncthreads();

    const int i = i0 + t;
    const float* tp = target + ((size_t)b * NPTS + i) * 3;
    const float px = tp[0], py = tp[1], pz = tp[2];

    float d0 = 3.4e38f, d1 = 3.4e38f, d2 = 3.4e38f;
    int   j0 = 0, j1 = 0, j2 = 0;
    #pragma unroll 4
    for (int j = 0; j < MSRC; j++) {
        const float dx = px - sx[j];
        const float dy = py - sy[j];
        const float dz = pz - sz[j];
        const float d  = dx * dx + dy * dy + dz * dz;
        if (d < d0)      { d2 = d1; j2 = j1; d1 = d0; j1 = j0; d0 = d; j0 = j; }
        else if (d < d1) { d2 = d1; j2 = j1; d1 = d;  j1 = j; }
        else if (d < d2) { d2 = d;  j2 = j; }
    }

    const float r0 = 1.0f / (d0 + 1e-8f);
    const float r1 = 1.0f / (d1 + 1e-8f);
    const float r2 = 1.0f / (d2 + 1e-8f);
    const float rs = 1.0f / (r0 + r1 + r2);
    s_idx[0][t] = j0; s_idx[1][t] = j1; s_idx[2][t] = j2;
    s_w [0][t] = r0 * rs; s_w[1][t] = r1 * rs; s_w[2][t] = r2 * rs;
    __syncthreads();

    // Phase 2: interpolate all C2 channels (channels 0..255 of X), coalesced writes
    const float* sf = sfeat + (size_t)b * C2 * MSRC;
    float*       Xb = X     + (size_t)b * CIN * NPTS;
    const int   a0 = s_idx[0][t], a1 = s_idx[1][t], a2 = s_idx[2][t];
    const float w0 = s_w[0][t],   w1 = s_w[1][t],   w2 = s_w[2][t];
    #pragma unroll 4
    for (int c = 0; c < C2; c++) {
        const float* row = sf + (size_t)c * MSRC;
        const float v = row[a0] * w0 + row[a1] * w1 + row[a2] * w2;
        Xb[(size_t)c * NPTS + i] = v;
    }
    // Channels 256..383 = target_feats copy (coalesced)
    const float* tf = tfeat + (size_t)b * C1 * NPTS;
    #pragma unroll 4
    for (int c = 0; c < C1; c++) {
        Xb[(size_t)(C2 + c) * NPTS + i] = tf[(size_t)c * NPTS + i];
    }
}

// ---------------------------------------------------------------------------
// Kernel 2: batched SGEMM + fused BN(eval) + ReLU
// C[b] = relu( scale ⊙ (A @ B[b]) + bias ),  A: (256,K) row-major, B[b]: (K,N)
// BM=128, BN=128, BK=16, 256 threads, 8x8 per-thread microtile.
// Grid: (N/128, 256/128, B_SZ)
// ---------------------------------------------------------------------------
__global__ void __launch_bounds__(256, 2)
gemm_bn_relu_kernel(const float* __restrict__ A,    // (CO, K)
                    const float* __restrict__ Bx,   // (B, K, N)
                    float* __restrict__ Cy,         // (B, CO, N)
                    const float* __restrict__ gam,
                    const float* __restrict__ bet,
                    const float* __restrict__ mu,
                    const float* __restrict__ var,
                    int K)
{
    constexpr int BM = 128, BN = 128, BK = 16, TM = 8, TN = 8;
    __shared__ float As[BK][BM];
    __shared__ float Bs[BK][BN];

    const int b  = blockIdx.z;
    const int n0 = blockIdx.x * BN;
    const int m0 = blockIdx.y * BM;
    const float* Bp = Bx + (size_t)b * K  * NPTS;
    float*       Cp = Cy + (size_t)b * CO * NPTS;

    const int tid  = threadIdx.x;
    const int rowA = tid >> 2;          // 0..63
    const int colA = (tid & 3) * 4;     // 0,4,8,12
    const int rowB = tid >> 5;          // 0..7
    const int colB = (tid & 31) * 4;    // 0..124
    const int tm   = (tid >> 4) * TM;   // 0..120
    const int tn   = (tid & 15) * TN;   // 0..120

    float acc[TM][TN];
    #pragma unroll
    for (int i = 0; i < TM; i++)
        #pragma unroll
        for (int j = 0; j < TN; j++) acc[i][j] = 0.0f;

    for (int k0 = 0; k0 < K; k0 += BK) {
        // A tile -> As[k][m] (transposed store)
        #pragma unroll
        for (int p = 0; p < 2; p++) {
            const int r = rowA + p * 64;
            const float4 v = *(const float4*)(A + (size_t)(m0 + r) * K + k0 + colA);
            As[colA + 0][r] = v.x;
            As[colA + 1][r] = v.y;
            As[colA + 2][r] = v.z;
            As[colA + 3][r] = v.w;
        }
        // B tile -> Bs[k][n]
        #pragma unroll
        for (int p = 0; p < 2; p++) {
            const int r = rowB + p * 8;
            const float4 v = *(const float4*)(Bp + (size_t)(k0 + r) * NPTS + n0 + colB);
            *(float4*)&Bs[r][colB] = v;
        }
        __syncthreads();

        #pragma unroll
        for (int kk = 0; kk < BK; kk++) {
            float a[TM], bv[TN];
            #pragma unroll
            for (int i = 0; i < TM; i += 4) *(float4*)&a[i]  = *(const float4*)&As[kk][tm + i];
            #pragma unroll
            for (int j = 0; j < TN; j += 4) *(float4*)&bv[j] = *(const float4*)&Bs[kk][tn + j];
            #pragma unroll
            for (int i = 0; i < TM; i++)
                #pragma unroll
                for (int j = 0; j < TN; j++)
                    acc[i][j] = fmaf(a[i], bv[j], acc[i][j]);
        }
        __syncthreads();
    }

    // Fused BN (eval) + ReLU epilogue, vectorized stores
    #pragma unroll
    for (int i = 0; i < TM; i++) {
        const int o = m0 + tm + i;
        const float s    = gam[o] * rsqrtf(var[o] + BN_EPS);
        const float bias = bet[o] - mu[o] * s;
        #pragma unroll
        for (int j = 0; j < TN; j += 4) {
            float4 v;
            v.x = fmaxf(acc[i][j + 0] * s + bias, 0.0f);
            v.y = fmaxf(acc[i][j + 1] * s + bias, 0.0f);
            v.z = fmaxf(acc[i][j + 2] * s + bias, 0.0f);
            v.w = fmaxf(acc[i][j + 3] * s + bias, 0.0f);
            *(float4*)(Cp + (size_t)o * NPTS + n0 + tn + j) = v;
        }
    }
}

// ---------------------------------------------------------------------------
extern "C" void kernel_launch(void* const* d_in, const int* in_sizes, int n_in,
                              void* d_out, int out_size)
{
    const float* target = (const float*)d_in[0];
    const float* source = (const float*)d_in[1];
    const float* tfeat  = (const float*)d_in[2];
    const float* sfeat  = (const float*)d_in[3];
    const float* w0     = (const float*)d_in[4];
    const float* g0     = (const float*)d_in[5];
    const float* b0     = (const float*)d_in[6];
    const float* mu0    = (const float*)d_in[7];
    const float* var0   = (const float*)d_in[8];
    const float* w1     = (const float*)d_in[9];
    const float* g1     = (const float*)d_in[10];
    const float* b1     = (const float*)d_in[11];
    const float* mu1    = (const float*)d_in[12];
    const float* var1   = (const float*)d_in[13];
    float* out = (float*)d_out;

    float* X;  cudaGetSymbolAddress((void**)&X,  g_X);
    float* Y0; cudaGetSymbolAddress((void**)&Y0, g_Y0);

    // 1) three_nn + interpolate + concat -> X (B, 384, N)
    {
        dim3 grid(NPTS / 128, B_SZ);
        interp_concat_kernel<<<grid, 128>>>(target, source, tfeat, sfeat, X);
    }
    // 2) layer 0: (256x384) @ X -> Y0, fused BN+ReLU
    {
        dim3 grid(NPTS / 128, CO / 128, B_SZ);
        gemm_bn_relu_kernel<<<grid, 256>>>(w0, X, Y0, g0, b0, mu0, var0, CIN);
    }
    // 3) layer 1: (256x256) @ Y0 -> out, fused BN+ReLU
    {
        dim3 grid(NPTS / 128, CO / 128, B_SZ);
        gemm_bn_relu_kernel<<<grid, 256>>>(w1, Y0, out, g1, b1, mu1, var1, CO);
    }
    (void)in_sizes; (void)n_in; (void)out_size;
}

// round 2
// speedup vs baseline: 1.6388x; 1.6388x over previous
#include <cuda_runtime.h>

#define B_SZ 8
#define NPTS 16384
#define MSRC 1024
#define C1   128
#define C2   256
#define CIN  384
#define CO   256
#define BN_EPS 1e-5f

// Scratch (allocation-free)
__device__ float g_Y0 [(size_t)B_SZ * CO * NPTS];    // layer-0 output, ~134 MB
__device__ float g_Zt [(size_t)B_SZ * MSRC * CO];    // (w0a @ sfeat)^T per batch, 8 MB
__device__ int4   g_nni[(size_t)B_SZ * NPTS];        // top-3 indices
__device__ float4 g_nnw[(size_t)B_SZ * NPTS];        // top-3 weights

// ---------------------------------------------------------------------------
// Kernel 1: three_nn only — top-3 by e = |s|^2 - 2 p·s (same ordering as d2),
// exact d2 recomputed for the 3 winners. Writes packed idx/wgt.
// Grid: (NPTS/256, B), 256 threads.
// ---------------------------------------------------------------------------
__global__ void __launch_bounds__(256)
three_nn_kernel(const float* __restrict__ target,   // (B, N, 3)
                const float* __restrict__ source,   // (B, M, 3)
                int4* __restrict__ nni,
                float4* __restrict__ nnw)
{
    const int b = blockIdx.y;
    const int t = threadIdx.x;
    const int i = blockIdx.x * 256 + t;

    __shared__ float4 s[MSRC];   // (x, y, z, |s|^2) — 16 KB

    const float* src = source + (size_t)b * MSRC * 3;
    for (int j = t; j < MSRC; j += 256) {
        const float x = src[j * 3 + 0];
        const float y = src[j * 3 + 1];
        const float z = src[j * 3 + 2];
        s[j] = make_float4(x, y, z, x * x + y * y + z * z);
    }
    __syncthreads();

    const float* tp = target + ((size_t)b * NPTS + i) * 3;
    const float px = tp[0], py = tp[1], pz = tp[2];
    const float qx = -2.0f * px, qy = -2.0f * py, qz = -2.0f * pz;

    float e0 = 3.4e38f, e1 = 3.4e38f, e2 = 3.4e38f;
    int   j0 = 0, j1 = 0, j2 = 0;
    #pragma unroll 8
    for (int j = 0; j < MSRC; j++) {
        const float4 v = s[j];
        const float e = fmaf(qx, v.x, fmaf(qy, v.y, fmaf(qz, v.z, v.w)));
        if (e < e0)      { e2 = e1; j2 = j1; e1 = e0; j1 = j0; e0 = e; j0 = j; }
        else if (e < e1) { e2 = e1; j2 = j1; e1 = e;  j1 = j; }
        else if (e < e2) { e2 = e;  j2 = j; }
    }

    // Exact squared distances for the 3 winners (matches reference arithmetic)
    float d[3]; int jj[3] = {j0, j1, j2};
    #pragma unroll
    for (int k = 0; k < 3; k++) {
        const float4 v = s[jj[k]];
        const float dx = px - v.x, dy = py - v.y, dz = pz - v.z;
        d[k] = dx * dx + dy * dy + dz * dz;
    }
    const float r0 = 1.0f / (d[0] + 1e-8f);
    const float r1 = 1.0f / (d[1] + 1e-8f);
    const float r2 = 1.0f / (d[2] + 1e-8f);
    const float rs = 1.0f / (r0 + r1 + r2);

    nni[(size_t)b * NPTS + i] = make_int4(j0, j1, j2, 0);
    nnw[(size_t)b * NPTS + i] = make_float4(r0 * rs, r1 * rs, r2 * rs, 0.0f);
}

// ---------------------------------------------------------------------------
// Kernel 2: Zt[b][j][o] = sum_c w0a[o][c] * sfeat[b][c][j]
// w0a = w0[:, 0:256] (lda=384). Small GEMM: M=1024(j) x N=256(o) x K=256.
// Grid: (MSRC/128, CO/128, B), 256 threads, 8x8 microtile.
// ---------------------------------------------------------------------------
__global__ void __launch_bounds__(256, 2)
zt_kernel(const float* __restrict__ w0,     // (256, 384) row-major
          const float* __restrict__ sfeat,  // (B, 256, 1024)
          float* __restrict__ Zt)           // (B, 1024, 256)
{
    constexpr int BK = 16, TM = 8, TN = 8;
    __shared__ float Ss[BK][128];   // sfeat tile [k][j]
    __shared__ float Ws[BK][128];   // w0a tile  [k][o]

    const int b  = blockIdx.z;
    const int J0 = blockIdx.x * 128;
    const int O0 = blockIdx.y * 128;
    const float* sf = sfeat + (size_t)b * C2 * MSRC;

    const int tid  = threadIdx.x;
    const int rowO = tid >> 2;          // 0..63
    const int colK = (tid & 3) * 4;     // 0,4,8,12
    const int rowK = tid >> 5;          // 0..7
    const int colJ = (tid & 31) * 4;    // 0..124
    const int tj   = (tid >> 4) * TM;
    const int to   = (tid & 15) * TN;

    float acc[TM][TN];
    #pragma unroll
    for (int i = 0; i < TM; i++)
        #pragma unroll
        for (int j = 0; j < TN; j++) acc[i][j] = 0.0f;

    for (int k0 = 0; k0 < C2; k0 += BK) {
        #pragma unroll
        for (int p = 0; p < 2; p++) {
            const int r = rowO + p * 64;
            const float4 v = *(const float4*)(w0 + (size_t)(O0 + r) * CIN + k0 + colK);
            Ws[colK + 0][r] = v.x;
            Ws[colK + 1][r] = v.y;
            Ws[colK + 2][r] = v.z;
            Ws[colK + 3][r] = v.w;
        }
        #pragma unroll
        for (int p = 0; p < 2; p++) {
            const int r = rowK + p * 8;
            const float4 v = *(const float4*)(sf + (size_t)(k0 + r) * MSRC + J0 + colJ);
            *(float4*)&Ss[r][colJ] = v;
        }
        __syncthreads();

        #pragma unroll
        for (int kk = 0; kk < BK; kk++) {
            float a[TM], w[TN];
            #pragma unroll
            for (int i = 0; i < TM; i += 4) *(float4*)&a[i] = *(const float4*)&Ss[kk][tj + i];
            #pragma unroll
            for (int j = 0; j < TN; j += 4) *(float4*)&w[j] = *(const float4*)&Ws[kk][to + j];
            #pragma unroll
            for (int i = 0; i < TM; i++)
                #pragma unroll
                for (int j = 0; j < TN; j++)
                    acc[i][j] = fmaf(a[i], w[j], acc[i][j]);
        }
        __syncthreads();
    }

    float* Zb = Zt + (size_t)b * MSRC * CO;
    #pragma unroll
    for (int i = 0; i < TM; i++) {
        #pragma unroll
        for (int j = 0; j < TN; j += 4) {
            float4 v = make_float4(acc[i][j], acc[i][j + 1], acc[i][j + 2], acc[i][j + 3]);
            *(float4*)(Zb + (size_t)(J0 + tj + i) * CO + O0 + to + j) = v;
        }
    }
}

// ---------------------------------------------------------------------------
// Kernel 3: batched SGEMM + optional interp-gather + fused BN(eval) + ReLU
// C[b] = relu( s ⊙ (A @ B[b] (+ gather(Zt))) + bias )
// BM=128, BN=128, BK=16, 256 threads, 8x8 microtile.
// ---------------------------------------------------------------------------
template<bool GATHER>
__global__ void __launch_bounds__(256, 2)
gemm_bn_relu_kernel(const float* __restrict__ A,    // (CO, lda)
                    int lda,
                    const float* __restrict__ Bx,   // (B, K, N)
                    float* __restrict__ Cy,         // (B, CO, N)
                    const float* __restrict__ gam,
                    const float* __restrict__ bet,
                    const float* __restrict__ mu,
                    const float* __restrict__ var,
                    int K,
                    const int4*   __restrict__ nni,
                    const float4* __restrict__ nnw,
                    const float*  __restrict__ Zt)
{
    constexpr int BM = 128, BN = 128, BK = 16, TM = 8, TN = 8;
    __shared__ float As[BK][BM];
    __shared__ float Bs[BK][BN];

    const int b  = blockIdx.z;
    const int n0 = blockIdx.x * BN;
    const int m0 = blockIdx.y * BM;
    const float* Bp = Bx + (size_t)b * K  * NPTS;
    float*       Cp = Cy + (size_t)b * CO * NPTS;

    const int tid  = threadIdx.x;
    const int rowA = tid >> 2;
    const int colA = (tid & 3) * 4;
    const int rowB = tid >> 5;
    const int colB = (tid & 31) * 4;
    const int tm   = (tid >> 4) * TM;
    const int tn   = (tid & 15) * TN;

    float acc[TM][TN];
    #pragma unroll
    for (int i = 0; i < TM; i++)
        #pragma unroll
        for (int j = 0; j < TN; j++) acc[i][j] = 0.0f;

    for (int k0 = 0; k0 < K; k0 += BK) {
        #pragma unroll
        for (int p = 0; p < 2; p++) {
            const int r = rowA + p * 64;
            const float4 v = *(const float4*)(A + (size_t)(m0 + r) * lda + k0 + colA);
            As[colA + 0][r] = v.x;
            As[colA + 1][r] = v.y;
            As[colA + 2][r] = v.z;
            As[colA + 3][r] = v.w;
        }
        #pragma unroll
        for (int p = 0; p < 2; p++) {
            const int r = rowB + p * 8;
            const float4 v = *(const float4*)(Bp + (size_t)(k0 + r) * NPTS + n0 + colB);
            *(float4*)&Bs[r][colB] = v;
        }
        __syncthreads();

        #pragma unroll
        for (int kk = 0; kk < BK; kk++) {
            float a[TM], bv[TN];
            #pragma unroll
            for (int i = 0; i < TM; i += 4) *(float4*)&a[i]  = *(const float4*)&As[kk][tm + i];
            #pragma unroll
            for (int j = 0; j < TN; j += 4) *(float4*)&bv[j] = *(const float4*)&Bs[kk][tn + j];
            #pragma unroll
            for (int i = 0; i < TM; i++)
                #pragma unroll
                for (int j = 0; j < TN; j++)
                    acc[i][j] = fmaf(a[i], bv[j], acc[i][j]);
        }
        __syncthreads();
    }

    // Interp contribution: acc[:, n] += sum_k wgt_k(n) * Zt[idx_k(n), m0+tm : +8]
    if (GATHER) {
        const float* Zb = Zt + (size_t)b * MSRC * CO;
        #pragma unroll
        for (int j = 0; j < TN; j++) {
            const int n = n0 + tn + j;
            const int4   ji = nni[(size_t)b * NPTS + n];
            const float4 jw = nnw[(size_t)b * NPTS + n];
            const float* z0 = Zb + (size_t)ji.x * CO + m0 + tm;
            const float* z1 = Zb + (size_t)ji.y * CO + m0 + tm;
            const float* z2 = Zb + (size_t)ji.z * CO + m0 + tm;
            #pragma unroll
            for (int i = 0; i < TM; i += 4) {
                const float4 a0 = *(const float4*)(z0 + i);
                const float4 a1 = *(const float4*)(z1 + i);
                const float4 a2 = *(const float4*)(z2 + i);
                acc[i + 0][j] += jw.x * a0.x + jw.y * a1.x + jw.z * a2.x;
                acc[i + 1][j] += jw.x * a0.y + jw.y * a1.y + jw.z * a2.y;
                acc[i + 2][j] += jw.x * a0.z + jw.y * a1.z + jw.z * a2.z;
                acc[i + 3][j] += jw.x * a0.w + jw.y * a1.w + jw.z * a2.w;
            }
        }
    }

    #pragma unroll
    for (int i = 0; i < TM; i++) {
        const int o = m0 + tm + i;
        const float s    = gam[o] * rsqrtf(var[o] + BN_EPS);
        const float bias = bet[o] - mu[o] * s;
        #pragma unroll
        for (int j = 0; j < TN; j += 4) {
            float4 v;
            v.x = fmaxf(acc[i][j + 0] * s + bias, 0.0f);
            v.y = fmaxf(acc[i][j + 1] * s + bias, 0.0f);
            v.z = fmaxf(acc[i][j + 2] * s + bias, 0.0f);
            v.w = fmaxf(acc[i][j + 3] * s + bias, 0.0f);
            *(float4*)(Cp + (size_t)o * NPTS + n0 + tn + j) = v;
        }
    }
}

// ---------------------------------------------------------------------------
extern "C" void kernel_launch(void* const* d_in, const int* in_sizes, int n_in,
                              void* d_out, int out_size)
{
    const float* target = (const float*)d_in[0];
    const float* source = (const float*)d_in[1];
    const float* tfeat  = (const float*)d_in[2];
    const float* sfeat  = (const float*)d_in[3];
    const float* w0     = (const float*)d_in[4];
    const float* g0     = (const float*)d_in[5];
    const float* b0     = (const float*)d_in[6];
    const float* mu0    = (const float*)d_in[7];
    const float* var0   = (const float*)d_in[8];
    const float* w1     = (const float*)d_in[9];
    const float* g1     = (const float*)d_in[10];
    const float* b1     = (const float*)d_in[11];
    const float* mu1    = (const float*)d_in[12];
    const float* var1   = (const float*)d_in[13];
    float* out = (float*)d_out;

    float*  Y0;  cudaGetSymbolAddress((void**)&Y0,  g_Y0);
    float*  Zt;  cudaGetSymbolAddress((void**)&Zt,  g_Zt);
    int4*   nni; cudaGetSymbolAddress((void**)&nni, g_nni);
    float4* nnw; cudaGetSymbolAddress((void**)&nnw, g_nnw);

    // 1) three_nn -> idx/wgt
    {
        dim3 grid(NPTS / 256, B_SZ);
        three_nn_kernel<<<grid, 256>>>(target, source, nni, nnw);
    }
    // 2) Zt = (w0[:, :256] @ sfeat)^T per batch  (B, 1024, 256)
    {
        dim3 grid(MSRC / 128, CO / 128, B_SZ);
        zt_kernel<<<grid, 256>>>(w0, sfeat, Zt);
    }
    // 3) layer 0: w0[:, 256:384] @ tfeat + gather(Zt) -> BN+ReLU -> Y0
    {
        dim3 grid(NPTS / 128, CO / 128, B_SZ);
        gemm_bn_relu_kernel<true><<<grid, 256>>>(w0 + C2, CIN, tfeat, Y0,
                                                 g0, b0, mu0, var0, C1,
                                                 nni, nnw, Zt);
    }
    // 4) layer 1: w1 @ Y0 -> BN+ReLU -> out
    {
        dim3 grid(NPTS / 128, CO / 128, B_SZ);
        gemm_bn_relu_kernel<false><<<grid, 256>>>(w1, CO, Y0, out,
                                                  g1, b1, mu1, var1, CO,
                                                  nullptr, nullptr, nullptr);
    }
    (void)in_sizes; (void)n_in; (void)out_size;
}

// round 4
// speedup vs baseline: 2.6009x; 1.5871x over previous
#include <cuda_runtime.h>
#include <cuda_bf16.h>
#include <cstdint>

#define B_SZ 8
#define NPTS 16384
#define MSRC 1024
#define C1   128
#define C2   256
#define CIN  384
#define CO   256
#define BN_EPS 1e-5f

// ---------------------------------------------------------------------------
// Scratch (allocation-free, 16B-aligned for cp.async / float4)
// ---------------------------------------------------------------------------
__device__ __align__(256) float  g_Zt [(size_t)B_SZ * MSRC * CO];
__device__ __align__(256) int4   g_nni[(size_t)B_SZ * NPTS];
__device__ __align__(256) float4 g_nnw[(size_t)B_SZ * NPTS];
__device__ __align__(256) __nv_bfloat16 g_W0h[CO * C1], g_W0l[CO * C1];
__device__ __align__(256) __nv_bfloat16 g_W1h[CO * CO], g_W1l[CO * CO];
__device__ __align__(256) __nv_bfloat16 g_Th [(size_t)B_SZ * NPTS * C1];
__device__ __align__(256) __nv_bfloat16 g_Tl [(size_t)B_SZ * NPTS * C1];
__device__ __align__(256) __nv_bfloat16 g_Y0h[(size_t)B_SZ * NPTS * CO];
__device__ __align__(256) __nv_bfloat16 g_Y0l[(size_t)B_SZ * NPTS * CO];

// ---------------------------------------------------------------------------
// PTX helpers (sm_100-safe: ldmatrix / mma.sync / cp.async only)
// ---------------------------------------------------------------------------
__device__ __forceinline__ uint32_t smem_u32(const void* p) {
    uint32_t a;
    asm("{ .reg .u64 t; cvta.to.shared.u64 t, %1; cvt.u32.u64 %0, t; }" : "=r"(a) : "l"(p));
    return a;
}
#define CP16(dst, src) \
    asm volatile("cp.async.cg.shared.global [%0], [%1], 16;" :: "r"(dst), "l"(src))
#define CP_COMMIT() asm volatile("cp.async.commit_group;" ::: "memory")
#define CP_WAIT(n)  asm volatile("cp.async.wait_group %0;" :: "n"(n) : "memory")

#define LDSM4(r, addr) \
    asm volatile("ldmatrix.sync.aligned.m8n8.x4.shared.b16 {%0,%1,%2,%3}, [%4];" \
        : "=r"((r)[0]), "=r"((r)[1]), "=r"((r)[2]), "=r"((r)[3]) : "r"(addr))

#define MMA_BF16(d, a, b0, b1) \
    asm volatile("mma.sync.aligned.m16n8k16.row.col.f32.bf16.bf16.f32 " \
        "{%0,%1,%2,%3}, {%4,%5,%6,%7}, {%8,%9}, {%0,%1,%2,%3};" \
        : "+f"((d)[0]), "+f"((d)[1]), "+f"((d)[2]), "+f"((d)[3]) \
        : "r"((a)[0]), "r"((a)[1]), "r"((a)[2]), "r"((a)[3]), "r"(b0), "r"(b1))

// ---------------------------------------------------------------------------
// three_nn (unchanged)
// ---------------------------------------------------------------------------
__global__ void __launch_bounds__(256)
three_nn_kernel(const float* __restrict__ target, const float* __restrict__ source,
                int4* __restrict__ nni, float4* __restrict__ nnw)
{
    const int b = blockIdx.y, t = threadIdx.x;
    const int i = blockIdx.x * 256 + t;
    __shared__ float4 s[MSRC];
    const float* src = source + (size_t)b * MSRC * 3;
    for (int j = t; j < MSRC; j += 256) {
        const float x = src[j * 3 + 0], y = src[j * 3 + 1], z = src[j * 3 + 2];
        s[j] = make_float4(x, y, z, x * x + y * y + z * z);
    }
    __syncthreads();
    const float* tp = target + ((size_t)b * NPTS + i) * 3;
    const float px = tp[0], py = tp[1], pz = tp[2];
    const float qx = -2.0f * px, qy = -2.0f * py, qz = -2.0f * pz;
    float e0 = 3.4e38f, e1 = 3.4e38f, e2 = 3.4e38f;
    int   j0 = 0, j1 = 0, j2 = 0;
    #pragma unroll 8
    for (int j = 0; j < MSRC; j++) {
        const float4 v = s[j];
        const float e = fmaf(qx, v.x, fmaf(qy, v.y, fmaf(qz, v.z, v.w)));
        if (e < e0)      { e2 = e1; j2 = j1; e1 = e0; j1 = j0; e0 = e; j0 = j; }
        else if (e < e1) { e2 = e1; j2 = j1; e1 = e;  j1 = j; }
        else if (e < e2) { e2 = e;  j2 = j; }
    }
    float d[3]; int jj[3] = {j0, j1, j2};
    #pragma unroll
    for (int k = 0; k < 3; k++) {
        const float4 v = s[jj[k]];
        const float dx = px - v.x, dy = py - v.y, dz = pz - v.z;
        d[k] = dx * dx + dy * dy + dz * dz;
    }
    const float r0 = 1.0f / (d[0] + 1e-8f), r1 = 1.0f / (d[1] + 1e-8f), r2 = 1.0f / (d[2] + 1e-8f);
    const float rs = 1.0f / (r0 + r1 + r2);
    nni[(size_t)b * NPTS + i] = make_int4(j0, j1, j2, 0);
    nnw[(size_t)b * NPTS + i] = make_float4(r0 * rs, r1 * rs, r2 * rs, 0.0f);
}

// ---------------------------------------------------------------------------
// Zt = (w0[:, :256] @ sfeat)^T per batch (fp32, unchanged)
// ---------------------------------------------------------------------------
__global__ void __launch_bounds__(256, 2)
zt_kernel(const float* __restrict__ w0, const float* __restrict__ sfeat, float* __restrict__ Zt)
{
    constexpr int BK = 16, TM = 8, TN = 8;
    __shared__ float Ss[BK][128];
    __shared__ float Ws[BK][128];
    const int b = blockIdx.z, J0 = blockIdx.x * 128, O0 = blockIdx.y * 128;
    const float* sf = sfeat + (size_t)b * C2 * MSRC;
    const int tid = threadIdx.x;
    const int rowO = tid >> 2, colK = (tid & 3) * 4;
    const int rowK = tid >> 5, colJ = (tid & 31) * 4;
    const int tj = (tid >> 4) * TM, to = (tid & 15) * TN;
    float acc[TM][TN];
    #pragma unroll
    for (int i = 0; i < TM; i++)
        #pragma unroll
        for (int j = 0; j < TN; j++) acc[i][j] = 0.0f;
    for (int k0 = 0; k0 < C2; k0 += BK) {
        #pragma unroll
        for (int p = 0; p < 2; p++) {
            const int r = rowO + p * 64;
            const float4 v = *(const float4*)(w0 + (size_t)(O0 + r) * CIN + k0 + colK);
            Ws[colK + 0][r] = v.x; Ws[colK + 1][r] = v.y;
            Ws[colK + 2][r] = v.z; Ws[colK + 3][r] = v.w;
        }
        #pragma unroll
        for (int p = 0; p < 2; p++) {
            const int r = rowK + p * 8;
            *(float4*)&Ss[r][colJ] = *(const float4*)(sf + (size_t)(k0 + r) * MSRC + J0 + colJ);
        }
        __syncthreads();
        #pragma unroll
        for (int kk = 0; kk < BK; kk++) {
            float a[TM], w[TN];
            #pragma unroll
            for (int i = 0; i < TM; i += 4) *(float4*)&a[i] = *(const float4*)&Ss[kk][tj + i];
            #pragma unroll
            for (int j = 0; j < TN; j += 4) *(float4*)&w[j] = *(const float4*)&Ws[kk][to + j];
            #pragma unroll
            for (int i = 0; i < TM; i++)
                #pragma unroll
                for (int j = 0; j < TN; j++) acc[i][j] = fmaf(a[i], w[j], acc[i][j]);
        }
        __syncthreads();
    }
    float* Zb = Zt + (size_t)b * MSRC * CO;
    #pragma unroll
    for (int i = 0; i < TM; i++)
        #pragma unroll
        for (int j = 0; j < TN; j += 4) {
            float4 v = make_float4(acc[i][j], acc[i][j+1], acc[i][j+2], acc[i][j+3]);
            *(float4*)(Zb + (size_t)(J0 + tj + i) * CO + O0 + to + j) = v;
        }
}

// ---------------------------------------------------------------------------
// Weight hi/lo split
// ---------------------------------------------------------------------------
__global__ void split_w_kernel(const float* __restrict__ w, int lda, int c0, int KW,
                               __nv_bfloat16* __restrict__ Wh, __nv_bfloat16* __restrict__ Wl)
{
    const int idx = blockIdx.x * 256 + threadIdx.x;
    if (idx >= CO * KW) return;
    const int o = idx / KW, k = idx % KW;
    const float x = w[(size_t)o * lda + c0 + k];
    const __nv_bfloat16 h = __float2bfloat16(x);
    Wh[idx] = h;
    Wl[idx] = __float2bfloat16(x - __bfloat162float(h));
}

// ---------------------------------------------------------------------------
// tfeat transpose + hi/lo split: (B,C1,N) fp32 -> (B,N,C1) bf16 x2
// ---------------------------------------------------------------------------
__global__ void __launch_bounds__(256)
tfeat_tsplit_kernel(const float* __restrict__ tfeat,
                    __nv_bfloat16* __restrict__ Th, __nv_bfloat16* __restrict__ Tl)
{
    __shared__ float sm[32][33];
    const int b = blockIdx.z;
    const int n0 = blockIdx.x * 32, c0 = blockIdx.y * 32;
    const int tx = threadIdx.x & 31, ty = threadIdx.x >> 5;
    const float* src = tfeat + (size_t)b * C1 * NPTS;
    #pragma unroll
    for (int i = 0; i < 4; i++) {
        const int c = ty + i * 8;
        sm[c][tx] = src[(size_t)(c0 + c) * NPTS + n0 + tx];
    }
    __syncthreads();
    #pragma unroll
    for (int i = 0; i < 4; i++) {
        const int n = ty + i * 8;
        const float x = sm[tx][n];
        const __nv_bfloat16 h = __float2bfloat16(x);
        const size_t idx = ((size_t)b * NPTS + n0 + n) * C1 + c0 + tx;
        Th[idx] = h;
        Tl[idx] = __float2bfloat16(x - __bfloat162float(h));
    }
}

// ---------------------------------------------------------------------------
// bf16x3 mma.sync GEMM + fused epilogue.
// D[o][n] = sum_k W[o,k] * X^T[n,k].  CTA tile 128(m) x 128(n), BK=64,
// 8 warps (4m x 2n), warp tile 32x64 via m16n8k16, cp.async double buffer.
// ---------------------------------------------------------------------------
template<int KW, bool L0GATHER>
__global__ void __launch_bounds__(256, 1)
mma_layer_kernel(const __nv_bfloat16* __restrict__ Wh, const __nv_bfloat16* __restrict__ Wl,
                 const __nv_bfloat16* __restrict__ Xh, const __nv_bfloat16* __restrict__ Xl,
                 float* __restrict__ outF,
                 __nv_bfloat16* __restrict__ outH, __nv_bfloat16* __restrict__ outL,
                 const float* __restrict__ gam, const float* __restrict__ bet,
                 const float* __restrict__ mu,  const float* __restrict__ var,
                 const int4* __restrict__ nni, const float4* __restrict__ nnw,
                 const float* __restrict__ Zt)
{
    constexpr int KC  = KW / 64;          // k-chunks
    constexpr int TS  = 128 * 72 * 2;     // 18432 B per tile (stride 72 halves = 144 B)
    constexpr int BUF = 4 * TS;           // Ah, Al, Bh, Bl
    extern __shared__ __align__(16) char smem[];
    const uint32_t sb = smem_u32(smem);

    const int tid = threadIdx.x, lane = tid & 31, wid = tid >> 5;
    const int wm = wid >> 1, wn = wid & 1;
    const int b = blockIdx.z, n0 = blockIdx.x * 128, m0 = blockIdx.y * 128;

    const __nv_bfloat16* Ah_g = Wh + (size_t)m0 * KW;
    const __nv_bfloat16* Al_g = Wl + (size_t)m0 * KW;
    const __nv_bfloat16* Bh_g = Xh + ((size_t)b * NPTS + n0) * KW;
    const __nv_bfloat16* Bl_g = Xl + ((size_t)b * NPTS + n0) * KW;

    const int lr = tid >> 3;         // base row (0..31), +32 per iter
    const int lc = (tid & 7) * 8;    // k offset in halves (0..56)

    float acc[2][8][4];
    #pragma unroll
    for (int i = 0; i < 2; i++)
        #pragma unroll
        for (int j = 0; j < 8; j++)
            #pragma unroll
            for (int q = 0; q < 4; q++) acc[i][j][q] = 0.0f;

    // -------- prologue: load chunk 0 into buffer 0 --------
    {
        const int k0 = 0;
        #pragma unroll
        for (int it = 0; it < 4; it++) {
            const int r = lr + it * 32;
            const uint32_t so = (uint32_t)(r * 144 + lc * 2);
            CP16(sb + so,          Ah_g + (size_t)r * KW + k0 + lc);
            CP16(sb + TS + so,     Al_g + (size_t)r * KW + k0 + lc);
            CP16(sb + 2*TS + so,   Bh_g + (size_t)r * KW + k0 + lc);
            CP16(sb + 3*TS + so,   Bl_g + (size_t)r * KW + k0 + lc);
        }
        CP_COMMIT();
    }

    for (int c = 0; c < KC; c++) {
        if (c + 1 < KC) {
            const int k0 = (c + 1) * 64;
            const uint32_t bufo = (uint32_t)(((c + 1) & 1) * BUF);
            #pragma unroll
            for (int it = 0; it < 4; it++) {
                const int r = lr + it * 32;
                const uint32_t so = bufo + (uint32_t)(r * 144 + lc * 2);
                CP16(sb + so,          Ah_g + (size_t)r * KW + k0 + lc);
                CP16(sb + TS + so,     Al_g + (size_t)r * KW + k0 + lc);
                CP16(sb + 2*TS + so,   Bh_g + (size_t)r * KW + k0 + lc);
                CP16(sb + 3*TS + so,   Bl_g + (size_t)r * KW + k0 + lc);
            }
            CP_COMMIT();
            CP_WAIT(1);
        } else {
            CP_WAIT(0);
        }
        __syncthreads();

        const uint32_t base = sb + (uint32_t)((c & 1) * BUF);
        #pragma unroll
        for (int kk = 0; kk < 4; kk++) {
            uint32_t ah[2][4], al[2][4];
            #pragma unroll
            for (int mt = 0; mt < 2; mt++) {
                const uint32_t ad = base
                    + (uint32_t)((wm * 32 + mt * 16 + (lane & 15)) * 144
                                 + (kk * 16 + ((lane >> 4) << 3)) * 2);
                LDSM4(ah[mt], ad);
                LDSM4(al[mt], ad + TS);
            }
            #pragma unroll
            for (int ng = 0; ng < 4; ng++) {
                uint32_t bh[4], bl[4];
                const uint32_t bd = base + 2 * TS
                    + (uint32_t)((wn * 64 + ng * 16 + (lane & 7) + ((lane >> 4) << 3)) * 144
                                 + (kk * 16 + (((lane >> 3) & 1) << 3)) * 2);
                LDSM4(bh, bd);
                LDSM4(bl, bd + TS);
                #pragma unroll
                for (int mt = 0; mt < 2; mt++) {
                    #pragma unroll
                    for (int hh = 0; hh < 2; hh++) {
                        float* d = acc[mt][ng * 2 + hh];
                        MMA_BF16(d, ah[mt], bh[2 * hh], bh[2 * hh + 1]);
                        MMA_BF16(d, ah[mt], bl[2 * hh], bl[2 * hh + 1]);
                        MMA_BF16(d, al[mt], bh[2 * hh], bh[2 * hh + 1]);
                    }
                }
            }
        }
        __syncthreads();
    }

    // ---------------- Epilogue ----------------
    if (!L0GATHER) {
        // BN + ReLU, direct fp32 stores to (B, CO, N)
        #pragma unroll
        for (int mt = 0; mt < 2; mt++) {
            const int o0 = m0 + wm * 32 + mt * 16 + (lane >> 2);
            const float s0 = gam[o0] * rsqrtf(var[o0] + BN_EPS);
            const float c0 = bet[o0] - mu[o0] * s0;
            const int o1 = o0 + 8;
            const float s1 = gam[o1] * rsqrtf(var[o1] + BN_EPS);
            const float c1 = bet[o1] - mu[o1] * s1;
            #pragma unroll
            for (int j = 0; j < 8; j++) {
                const int n = n0 + wn * 64 + j * 8 + (lane & 3) * 2;
                float2 v0, v1;
                v0.x = fmaxf(fmaf(acc[mt][j][0], s0, c0), 0.0f);
                v0.y = fmaxf(fmaf(acc[mt][j][1], s0, c0), 0.0f);
                v1.x = fmaxf(fmaf(acc[mt][j][2], s1, c1), 0.0f);
                v1.y = fmaxf(fmaf(acc[mt][j][3], s1, c1), 0.0f);
                *(float2*)(outF + ((size_t)b * CO + o0) * NPTS + n) = v0;
                *(float2*)(outF + ((size_t)b * CO + o1) * NPTS + n) = v1;
            }
        }
    } else {
        // Bounce raw accumulators through smem as S[n][o] fp32 (stride 132)
        float* S = (float*)smem;
        #pragma unroll
        for (int mt = 0; mt < 2; mt++) {
            const int ol = wm * 32 + mt * 16 + (lane >> 2);
            #pragma unroll
            for (int j = 0; j < 8; j++) {
                const int nl = wn * 64 + j * 8 + (lane & 3) * 2;
                S[(nl + 0) * 132 + ol]     = acc[mt][j][0];
                S[(nl + 1) * 132 + ol]     = acc[mt][j][1];
                S[(nl + 0) * 132 + ol + 8] = acc[mt][j][2];
                S[(nl + 1) * 132 + ol + 8] = acc[mt][j][3];
            }
        }
        __syncthreads();

        // Cooperative pass: gather(Zt) + BN + ReLU -> Y0^T bf16 hi/lo planes
        const size_t bn = (size_t)b * NPTS;
        const float* Zb = Zt + (size_t)b * MSRC * CO;
        #pragma unroll 2
        for (int it = 0; it < 16; it++) {
            const int item = tid + it * 256;
            const int nl = item >> 5, o4 = (item & 31) * 4;
            const int n = n0 + nl, o = m0 + o4;
            float4 v = *(float4*)(S + nl * 132 + o4);
            const int4   ji = nni[bn + n];
            const float4 jw = nnw[bn + n];
            const float4 z0 = *(const float4*)(Zb + (size_t)ji.x * CO + o);
            const float4 z1 = *(const float4*)(Zb + (size_t)ji.y * CO + o);
            const float4 z2 = *(const float4*)(Zb + (size_t)ji.z * CO + o);
            v.x += jw.x * z0.x + jw.y * z1.x + jw.z * z2.x;
            v.y += jw.x * z0.y + jw.y * z1.y + jw.z * z2.y;
            v.z += jw.x * z0.z + jw.y * z1.z + jw.z * z2.z;
            v.w += jw.x * z0.w + jw.y * z1.w + jw.z * z2.w;
            const float4 g4 = *(const float4*)(gam + o);
            const float4 b4 = *(const float4*)(bet + o);
            const float4 m4 = *(const float4*)(mu  + o);
            const float4 q4 = *(const float4*)(var + o);
            float4 y;
            float sx = g4.x * rsqrtf(q4.x + BN_EPS);
            float sy = g4.y * rsqrtf(q4.y + BN_EPS);
            float sz = g4.z * rsqrtf(q4.z + BN_EPS);
            float sw = g4.w * rsqrtf(q4.w + BN_EPS);
            y.x = fmaxf(fmaf(v.x, sx, b4.x - m4.x * sx), 0.0f);
            y.y = fmaxf(fmaf(v.y, sy, b4.y - m4.y * sy), 0.0f);
            y.z = fmaxf(fmaf(v.z, sz, b4.z - m4.z * sz), 0.0f);
            y.w = fmaxf(fmaf(v.w, sw, b4.w - m4.w * sw), 0.0f);
            union { __nv_bfloat16 h[4]; uint2 u; } H, L;
            H.h[0] = __float2bfloat16(y.x); L.h[0] = __float2bfloat16(y.x - __bfloat162float(H.h[0]));
            H.h[1] = __float2bfloat16(y.y); L.h[1] = __float2bfloat16(y.y - __bfloat162float(H.h[1]));
            H.h[2] = __float2bfloat16(y.z); L.h[2] = __float2bfloat16(y.z - __bfloat162float(H.h[2]));
            H.h[3] = __float2bfloat16(y.w); L.h[3] = __float2bfloat16(y.w - __bfloat162float(H.h[3]));
            *(uint2*)(outH + (bn + n) * CO + o) = H.u;
            *(uint2*)(outL + (bn + n) * CO + o) = L.u;
        }
    }
}

// ---------------------------------------------------------------------------
extern "C" void kernel_launch(void* const* d_in, const int* in_sizes, int n_in,
                              void* d_out, int out_size)
{
    const float* target = (const float*)d_in[0];
    const float* source = (const float*)d_in[1];
    const float* tfeat  = (const float*)d_in[2];
    const float* sfeat  = (const float*)d_in[3];
    const float* w0     = (const float*)d_in[4];
    const float* g0     = (const float*)d_in[5];
    const float* b0     = (const float*)d_in[6];
    const float* mu0    = (const float*)d_in[7];
    const float* var0   = (const float*)d_in[8];
    const float* w1     = (const float*)d_in[9];
    const float* g1     = (const float*)d_in[10];
    const float* b1     = (const float*)d_in[11];
    const float* mu1    = (const float*)d_in[12];
    const float* var1   = (const float*)d_in[13];
    float* out = (float*)d_out;

    float*  Zt;  cudaGetSymbolAddress((void**)&Zt,  g_Zt);
    int4*   nni; cudaGetSymbolAddress((void**)&nni, g_nni);
    float4* nnw; cudaGetSymbolAddress((void**)&nnw, g_nnw);
    __nv_bfloat16 *W0h, *W0l, *W1h, *W1l, *Th, *Tl, *Y0h, *Y0l;
    cudaGetSymbolAddress((void**)&W0h, g_W0h); cudaGetSymbolAddress((void**)&W0l, g_W0l);
    cudaGetSymbolAddress((void**)&W1h, g_W1h); cudaGetSymbolAddress((void**)&W1l, g_W1l);
    cudaGetSymbolAddress((void**)&Th,  g_Th);  cudaGetSymbolAddress((void**)&Tl,  g_Tl);
    cudaGetSymbolAddress((void**)&Y0h, g_Y0h); cudaGetSymbolAddress((void**)&Y0l, g_Y0l);

    constexpr int SMEM_MMA = 2 * 4 * 128 * 72 * 2;  // 147456 B
    cudaFuncSetAttribute(mma_layer_kernel<C1, true>,
                         cudaFuncAttributeMaxDynamicSharedMemorySize, SMEM_MMA);
    cudaFuncSetAttribute(mma_layer_kernel<CO, false>,
                         cudaFuncAttributeMaxDynamicSharedMemorySize, SMEM_MMA);

    // 1) three_nn
    {
        dim3 grid(NPTS / 256, B_SZ);
        three_nn_kernel<<<grid, 256>>>(target, source, nni, nnw);
    }
    // 2) Zt = (w0[:, :256] @ sfeat)^T
    {
        dim3 grid(MSRC / 128, CO / 128, B_SZ);
        zt_kernel<<<grid, 256>>>(w0, sfeat, Zt);
    }
    // 3) weight splits
    split_w_kernel<<<(CO * C1 + 255) / 256, 256>>>(w0, CIN, C2, C1, W0h, W0l);
    split_w_kernel<<<(CO * CO + 255) / 256, 256>>>(w1, CO, 0, CO, W1h, W1l);
    // 4) tfeat transpose+split
    {
        dim3 grid(NPTS / 32, C1 / 32, B_SZ);
        tfeat_tsplit_kernel<<<grid, 256>>>(tfeat, Th, Tl);
    }
    // 5) layer 0: W0b @ tfeat^T + gather(Zt) + BN + ReLU -> Y0^T planes
    {
        dim3 grid(NPTS / 128, CO / 128, B_SZ);
        mma_layer_kernel<C1, true><<<grid, 256, SMEM_MMA>>>(
            W0h, W0l, Th, Tl, nullptr, Y0h, Y0l,
            g0, b0, mu0, var0, nni, nnw, Zt);
    }
    // 6) layer 1: W1 @ Y0^T + BN + ReLU -> out (B, CO, N) fp32
    {
        dim3 grid(NPTS / 128, CO / 128, B_SZ);
        mma_layer_kernel<CO, false><<<grid, 256, SMEM_MMA>>>(
            W1h, W1l, Y0h, Y0l, out, nullptr, nullptr,
            g1, b1, mu1, var1, nullptr, nullptr, nullptr);
    }
    (void)in_sizes; (void)n_in; (void)out_size;
}

// round 6
// speedup vs baseline: 3.5025x; 1.3466x over previous
#include <cuda_runtime.h>
#include <cuda_fp16.h>
#include <cstdint>

#define B_SZ 8
#define NPTS 16384
#define MSRC 1024
#define C1   128
#define C2   256
#define CIN  384
#define CO   256
#define BN_EPS 1e-5f

// ---------------------------------------------------------------------------
// Scratch (allocation-free)
// ---------------------------------------------------------------------------
__device__ __align__(256) float  g_Zt [(size_t)B_SZ * MSRC * CO];
__device__ __align__(256) int4   g_nni[(size_t)B_SZ * NPTS];
__device__ __align__(256) float4 g_nnw[(size_t)B_SZ * NPTS];
__device__ __align__(256) __half g_W0h[CO * C1], g_W0l[CO * C1];
__device__ __align__(256) __half g_W1h[CO * CO], g_W1l[CO * CO];
__device__ __align__(256) __half g_T  [(size_t)B_SZ * NPTS * C1];   // tfeat^T fp16
__device__ __align__(256) __half g_Y0 [(size_t)B_SZ * NPTS * CO];   // Y0^T fp16

// ---------------------------------------------------------------------------
// PTX helpers (sm_100-safe)
// ---------------------------------------------------------------------------
__device__ __forceinline__ uint32_t smem_u32(const void* p) {
    uint32_t a;
    asm("{ .reg .u64 t; cvta.to.shared.u64 t, %1; cvt.u32.u64 %0, t; }" : "=r"(a) : "l"(p));
    return a;
}
#define CP16(dst, src) \
    asm volatile("cp.async.cg.shared.global [%0], [%1], 16;" :: "r"(dst), "l"(src))
#define CP_COMMIT() asm volatile("cp.async.commit_group;" ::: "memory")
#define CP_WAIT(n)  asm volatile("cp.async.wait_group %0;" :: "n"(n) : "memory")

#define LDSM4(r, addr) \
    asm volatile("ldmatrix.sync.aligned.m8n8.x4.shared.b16 {%0,%1,%2,%3}, [%4];" \
        : "=r"((r)[0]), "=r"((r)[1]), "=r"((r)[2]), "=r"((r)[3]) : "r"(addr))

#define MMA_F16(d, a, b0, b1) \
    asm volatile("mma.sync.aligned.m16n8k16.row.col.f32.f16.f16.f32 " \
        "{%0,%1,%2,%3}, {%4,%5,%6,%7}, {%8,%9}, {%0,%1,%2,%3};" \
        : "+f"((d)[0]), "+f"((d)[1]), "+f"((d)[2]), "+f"((d)[3]) \
        : "r"((a)[0]), "r"((a)[1]), "r"((a)[2]), "r"((a)[3]), "r"(b0), "r"(b1))

// ---------------------------------------------------------------------------
// three_nn (unchanged)
// ---------------------------------------------------------------------------
__global__ void __launch_bounds__(256)
three_nn_kernel(const float* __restrict__ target, const float* __restrict__ source,
                int4* __restrict__ nni, float4* __restrict__ nnw)
{
    const int b = blockIdx.y, t = threadIdx.x;
    const int i = blockIdx.x * 256 + t;
    __shared__ float4 s[MSRC];
    const float* src = source + (size_t)b * MSRC * 3;
    for (int j = t; j < MSRC; j += 256) {
        const float x = src[j * 3 + 0], y = src[j * 3 + 1], z = src[j * 3 + 2];
        s[j] = make_float4(x, y, z, x * x + y * y + z * z);
    }
    __syncthreads();
    const float* tp = target + ((size_t)b * NPTS + i) * 3;
    const float px = tp[0], py = tp[1], pz = tp[2];
    const float qx = -2.0f * px, qy = -2.0f * py, qz = -2.0f * pz;
    float e0 = 3.4e38f, e1 = 3.4e38f, e2 = 3.4e38f;
    int   j0 = 0, j1 = 0, j2 = 0;
    #pragma unroll 8
    for (int j = 0; j < MSRC; j++) {
        const float4 v = s[j];
        const float e = fmaf(qx, v.x, fmaf(qy, v.y, fmaf(qz, v.z, v.w)));
        if (e < e0)      { e2 = e1; j2 = j1; e1 = e0; j1 = j0; e0 = e; j0 = j; }
        else if (e < e1) { e2 = e1; j2 = j1; e1 = e;  j1 = j; }
        else if (e < e2) { e2 = e;  j2 = j; }
    }
    float d[3]; int jj[3] = {j0, j1, j2};
    #pragma unroll
    for (int k = 0; k < 3; k++) {
        const float4 v = s[jj[k]];
        const float dx = px - v.x, dy = py - v.y, dz = pz - v.z;
        d[k] = dx * dx + dy * dy + dz * dz;
    }
    const float r0 = 1.0f / (d[0] + 1e-8f), r1 = 1.0f / (d[1] + 1e-8f), r2 = 1.0f / (d[2] + 1e-8f);
    const float rs = 1.0f / (r0 + r1 + r2);
    nni[(size_t)b * NPTS + i] = make_int4(j0, j1, j2, 0);
    nnw[(size_t)b * NPTS + i] = make_float4(r0 * rs, r1 * rs, r2 * rs, 0.0f);
}

// ---------------------------------------------------------------------------
// Zt = (w0[:, :256] @ sfeat)^T per batch (fp32, unchanged)
// ---------------------------------------------------------------------------
__global__ void __launch_bounds__(256, 2)
zt_kernel(const float* __restrict__ w0, const float* __restrict__ sfeat, float* __restrict__ Zt)
{
    constexpr int BK = 16, TM = 8, TN = 8;
    __shared__ float Ss[BK][128];
    __shared__ float Ws[BK][128];
    const int b = blockIdx.z, J0 = blockIdx.x * 128, O0 = blockIdx.y * 128;
    const float* sf = sfeat + (size_t)b * C2 * MSRC;
    const int tid = threadIdx.x;
    const int rowO = tid >> 2, colK = (tid & 3) * 4;
    const int rowK = tid >> 5, colJ = (tid & 31) * 4;
    const int tj = (tid >> 4) * TM, to = (tid & 15) * TN;
    float acc[TM][TN];
    #pragma unroll
    for (int i = 0; i < TM; i++)
        #pragma unroll
        for (int j = 0; j < TN; j++) acc[i][j] = 0.0f;
    for (int k0 = 0; k0 < C2; k0 += BK) {
        #pragma unroll
        for (int p = 0; p < 2; p++) {
            const int r = rowO + p * 64;
            const float4 v = *(const float4*)(w0 + (size_t)(O0 + r) * CIN + k0 + colK);
            Ws[colK + 0][r] = v.x; Ws[colK + 1][r] = v.y;
            Ws[colK + 2][r] = v.z; Ws[colK + 3][r] = v.w;
        }
        #pragma unroll
        for (int p = 0; p < 2; p++) {
            const int r = rowK + p * 8;
            *(float4*)&Ss[r][colJ] = *(const float4*)(sf + (size_t)(k0 + r) * MSRC + J0 + colJ);
        }
        __syncthreads();
        #pragma unroll
        for (int kk = 0; kk < BK; kk++) {
            float a[TM], w[TN];
            #pragma unroll
            for (int i = 0; i < TM; i += 4) *(float4*)&a[i] = *(const float4*)&Ss[kk][tj + i];
            #pragma unroll
            for (int j = 0; j < TN; j += 4) *(float4*)&w[j] = *(const float4*)&Ws[kk][to + j];
            #pragma unroll
            for (int i = 0; i < TM; i++)
                #pragma unroll
                for (int j = 0; j < TN; j++) acc[i][j] = fmaf(a[i], w[j], acc[i][j]);
        }
        __syncthreads();
    }
    float* Zb = Zt + (size_t)b * MSRC * CO;
    #pragma unroll
    for (int i = 0; i < TM; i++)
        #pragma unroll
        for (int j = 0; j < TN; j += 4) {
            float4 v = make_float4(acc[i][j], acc[i][j+1], acc[i][j+2], acc[i][j+3]);
            *(float4*)(Zb + (size_t)(J0 + tj + i) * CO + O0 + to + j) = v;
        }
}

// ---------------------------------------------------------------------------
// Weight hi/lo split (fp16 planes)
// ---------------------------------------------------------------------------
__global__ void split_w_kernel(const float* __restrict__ w, int lda, int c0, int KW,
                               __half* __restrict__ Wh, __half* __restrict__ Wl)
{
    const int idx = blockIdx.x * 256 + threadIdx.x;
    if (idx >= CO * KW) return;
    const int o = idx / KW, k = idx % KW;
    const float x = w[(size_t)o * lda + c0 + k];
    const __half h = __float2half_rn(x);
    Wh[idx] = h;
    Wl[idx] = __float2half_rn(x - __half2float(h));
}

// ---------------------------------------------------------------------------
// tfeat transpose: (B,C1,N) fp32 -> (B,N,C1) fp16
// ---------------------------------------------------------------------------
__global__ void __launch_bounds__(256)
tfeat_t_kernel(const float* __restrict__ tfeat, __half* __restrict__ T)
{
    __shared__ float sm[32][33];
    const int b = blockIdx.z;
    const int n0 = blockIdx.x * 32, c0 = blockIdx.y * 32;
    const int tx = threadIdx.x & 31, ty = threadIdx.x >> 5;
    const float* src = tfeat + (size_t)b * C1 * NPTS;
    #pragma unroll
    for (int i = 0; i < 4; i++) {
        const int c = ty + i * 8;
        sm[c][tx] = src[(size_t)(c0 + c) * NPTS + n0 + tx];
    }
    __syncthreads();
    #pragma unroll
    for (int i = 0; i < 4; i++) {
        const int n = ty + i * 8;
        T[((size_t)b * NPTS + n0 + n) * C1 + c0 + tx] = __float2half_rn(sm[tx][n]);
    }
}

// ---------------------------------------------------------------------------
// fp16 2-pass mma.sync GEMM + fused epilogue.
// D[o][n] = sum_k (Wh+Wl)[o,k] * X^T[n,k].  CTA tile 128m x 128n, BK=32,
// 8 warps (4m x 2n), double-buffered cp.async, 2 CTAs/SM.
// ---------------------------------------------------------------------------
template<int KW, bool L0GATHER>
__global__ void __launch_bounds__(256, 2)
mma_layer_kernel(const __half* __restrict__ Wh, const __half* __restrict__ Wl,
                 const __half* __restrict__ X,
                 float* __restrict__ outF, __half* __restrict__ outH,
                 const float* __restrict__ gam, const float* __restrict__ bet,
                 const float* __restrict__ mu,  const float* __restrict__ var,
                 const int4* __restrict__ nni, const float4* __restrict__ nnw,
                 const float* __restrict__ Zt)
{
    constexpr int KC  = KW / 32;
    constexpr int TS  = 128 * 80;     // bytes per tile (row stride 40 halves = 80 B)
    constexpr int BUF = 3 * TS;       // Ah, Al, B
    extern __shared__ __align__(16) char smem[];
    const uint32_t sb = smem_u32(smem);

    const int tid = threadIdx.x, lane = tid & 31, wid = tid >> 5;
    const int wm = wid >> 1, wn = wid & 1;
    const int b = blockIdx.z, n0 = blockIdx.x * 128, m0 = blockIdx.y * 128;

    const __half* Ah_g = Wh + (size_t)m0 * KW;
    const __half* Al_g = Wl + (size_t)m0 * KW;
    const __half* B_g  = X  + ((size_t)b * NPTS + n0) * KW;

    const int lr = tid >> 2;         // row 0..63, +64 per iter
    const int lc = (tid & 3) * 8;    // k offset in halves: 0,8,16,24

    float acc[2][8][4];
    #pragma unroll
    for (int i = 0; i < 2; i++)
        #pragma unroll
        for (int j = 0; j < 8; j++)
            #pragma unroll
            for (int q = 0; q < 4; q++) acc[i][j][q] = 0.0f;

    // prologue: chunk 0 -> buffer 0
    #pragma unroll
    for (int it = 0; it < 2; it++) {
        const int r = lr + it * 64;
        const uint32_t so = (uint32_t)(r * 80 + lc * 2);
        CP16(sb + so,          Ah_g + (size_t)r * KW + lc);
        CP16(sb + TS + so,     Al_g + (size_t)r * KW + lc);
        CP16(sb + 2*TS + so,   B_g  + (size_t)r * KW + lc);
    }
    CP_COMMIT();

    for (int c = 0; c < KC; c++) {
        if (c + 1 < KC) {
            const int k0 = (c + 1) * 32;
            const uint32_t bufo = (uint32_t)(((c + 1) & 1) * BUF);
            #pragma unroll
            for (int it = 0; it < 2; it++) {
                const int r = lr + it * 64;
                const uint32_t so = bufo + (uint32_t)(r * 80 + lc * 2);
                CP16(sb + so,          Ah_g + (size_t)r * KW + k0 + lc);
                CP16(sb + TS + so,     Al_g + (size_t)r * KW + k0 + lc);
                CP16(sb + 2*TS + so,   B_g  + (size_t)r * KW + k0 + lc);
            }
            CP_COMMIT();
            CP_WAIT(1);
        } else {
            CP_WAIT(0);
        }
        __syncthreads();

        const uint32_t base = sb + (uint32_t)((c & 1) * BUF);
        #pragma unroll
        for (int kk = 0; kk < 2; kk++) {
            uint32_t ah[2][4], al[2][4];
            #pragma unroll
            for (int mt = 0; mt < 2; mt++) {
                const uint32_t ad = base
                    + (uint32_t)((wm * 32 + mt * 16 + (lane & 15)) * 80
                                 + (kk * 16 + ((lane >> 4) << 3)) * 2);
                LDSM4(ah[mt], ad);
                LDSM4(al[mt], ad + TS);
            }
            #pragma unroll
            for (int ng = 0; ng < 4; ng++) {
                uint32_t bh[4];
                const uint32_t bd = base + 2 * TS
                    + (uint32_t)((wn * 64 + ng * 16 + (lane & 7) + ((lane >> 4) << 3)) * 80
                                 + (kk * 16 + (((lane >> 3) & 1) << 3)) * 2);
                LDSM4(bh, bd);
                #pragma unroll
                for (int mt = 0; mt < 2; mt++) {
                    #pragma unroll
                    for (int hh = 0; hh < 2; hh++) {
                        float* d = acc[mt][ng * 2 + hh];
                        MMA_F16(d, ah[mt], bh[2 * hh], bh[2 * hh + 1]);
                        MMA_F16(d, al[mt], bh[2 * hh], bh[2 * hh + 1]);
                    }
                }
            }
        }
        __syncthreads();
    }

    // ---------------- Epilogue ----------------
    if (!L0GATHER) {
        #pragma unroll
        for (int mt = 0; mt < 2; mt++) {
            const int o0 = m0 + wm * 32 + mt * 16 + (lane >> 2);
            const float s0 = gam[o0] * rsqrtf(var[o0] + BN_EPS);
            const float c0 = bet[o0] - mu[o0] * s0;
            const int o1 = o0 + 8;
            const float s1 = gam[o1] * rsqrtf(var[o1] + BN_EPS);
            const float c1 = bet[o1] - mu[o1] * s1;
            #pragma unroll
            for (int j = 0; j < 8; j++) {
                const int n = n0 + wn * 64 + j * 8 + (lane & 3) * 2;
                float2 v0, v1;
                v0.x = fmaxf(fmaf(acc[mt][j][0], s0, c0), 0.0f);
                v0.y = fmaxf(fmaf(acc[mt][j][1], s0, c0), 0.0f);
                v1.x = fmaxf(fmaf(acc[mt][j][2], s1, c1), 0.0f);
                v1.y = fmaxf(fmaf(acc[mt][j][3], s1, c1), 0.0f);
                *(float2*)(outF + ((size_t)b * CO + o0) * NPTS + n) = v0;
                *(float2*)(outF + ((size_t)b * CO + o1) * NPTS + n) = v1;
            }
        }
    } else {
        // Bounce accumulators to smem as S[n][o] fp32 (stride 132)
        float* S = (float*)smem;
        #pragma unroll
        for (int mt = 0; mt < 2; mt++) {
            const int ol = wm * 32 + mt * 16 + (lane >> 2);
            #pragma unroll
            for (int j = 0; j < 8; j++) {
                const int nl = wn * 64 + j * 8 + (lane & 3) * 2;
                S[(nl + 0) * 132 + ol]     = acc[mt][j][0];
                S[(nl + 1) * 132 + ol]     = acc[mt][j][1];
                S[(nl + 0) * 132 + ol + 8] = acc[mt][j][2];
                S[(nl + 1) * 132 + ol + 8] = acc[mt][j][3];
            }
        }
        __syncthreads();

        const size_t bn = (size_t)b * NPTS;
        const float* Zb = Zt + (size_t)b * MSRC * CO;
        #pragma unroll 2
        for (int it = 0; it < 16; it++) {
            const int item = tid + it * 256;
            const int nl = item >> 5, o4 = (item & 31) * 4;
            const int n = n0 + nl, o = m0 + o4;
            float4 v = *(float4*)(S + nl * 132 + o4);
            const int4   ji = nni[bn + n];
            const float4 jw = nnw[bn + n];
            const float4 z0 = *(const float4*)(Zb + (size_t)ji.x * CO + o);
            const float4 z1 = *(const float4*)(Zb + (size_t)ji.y * CO + o);
            const float4 z2 = *(const float4*)(Zb + (size_t)ji.z * CO + o);
            v.x += jw.x * z0.x + jw.y * z1.x + jw.z * z2.x;
            v.y += jw.x * z0.y + jw.y * z1.y + jw.z * z2.y;
            v.z += jw.x * z0.z + jw.y * z1.z + jw.z * z2.z;
            v.w += jw.x * z0.w + jw.y * z1.w + jw.z * z2.w;
            const float4 g4 = *(const float4*)(gam + o);
            const float4 b4 = *(const float4*)(bet + o);
            const float4 m4 = *(const float4*)(mu  + o);
            const float4 q4 = *(const float4*)(var + o);
            const float sx = g4.x * rsqrtf(q4.x + BN_EPS);
            const float sy = g4.y * rsqrtf(q4.y + BN_EPS);
            const float sz = g4.z * rsqrtf(q4.z + BN_EPS);
            const float sw = g4.w * rsqrtf(q4.w + BN_EPS);
            union { __half h[4]; uint2 u; } H;
            H.h[0] = __float2half_rn(fmaxf(fmaf(v.x, sx, b4.x - m4.x * sx), 0.0f));
            H.h[1] = __float2half_rn(fmaxf(fmaf(v.y, sy, b4.y - m4.y * sy), 0.0f));
            H.h[2] = __float2half_rn(fmaxf(fmaf(v.z, sz, b4.z - m4.z * sz), 0.0f));
            H.h[3] = __float2half_rn(fmaxf(fmaf(v.w, sw, b4.w - m4.w * sw), 0.0f));
            *(uint2*)(outH + (bn + n) * CO + o) = H.u;
        }
    }
}

// ---------------------------------------------------------------------------
extern "C" void kernel_launch(void* const* d_in, const int* in_sizes, int n_in,
                              void* d_out, int out_size)
{
    const float* target = (const float*)d_in[0];
    const float* source = (const float*)d_in[1];
    const float* tfeat  = (const float*)d_in[2];
    const float* sfeat  = (const float*)d_in[3];
    const float* w0     = (const float*)d_in[4];
    const float* g0     = (const float*)d_in[5];
    const float* b0     = (const float*)d_in[6];
    const float* mu0    = (const float*)d_in[7];
    const float* var0   = (const float*)d_in[8];
    const float* w1     = (const float*)d_in[9];
    const float* g1     = (const float*)d_in[10];
    const float* b1     = (const float*)d_in[11];
    const float* mu1    = (const float*)d_in[12];
    const float* var1   = (const float*)d_in[13];
    float* out = (float*)d_out;

    float*  Zt;  cudaGetSymbolAddress((void**)&Zt,  g_Zt);
    int4*   nni; cudaGetSymbolAddress((void**)&nni, g_nni);
    float4* nnw; cudaGetSymbolAddress((void**)&nnw, g_nnw);
    __half *W0h, *W0l, *W1h, *W1l, *T, *Y0;
    cudaGetSymbolAddress((void**)&W0h, g_W0h); cudaGetSymbolAddress((void**)&W0l, g_W0l);
    cudaGetSymbolAddress((void**)&W1h, g_W1h); cudaGetSymbolAddress((void**)&W1l, g_W1l);
    cudaGetSymbolAddress((void**)&T,   g_T);   cudaGetSymbolAddress((void**)&Y0,  g_Y0);

    constexpr int SMEM_L0 = 128 * 132 * 4;     // 67584 (bounce) > 61440 (mma bufs)
    constexpr int SMEM_L1 = 2 * 3 * 128 * 80;  // 61440
    cudaFuncSetAttribute(mma_layer_kernel<C1, true>,
                         cudaFuncAttributeMaxDynamicSharedMemorySize, SMEM_L0);
    cudaFuncSetAttribute(mma_layer_kernel<CO, false>,
                         cudaFuncAttributeMaxDynamicSharedMemorySize, SMEM_L1);

    // 1) three_nn
    {
        dim3 grid(NPTS / 256, B_SZ);
        three_nn_kernel<<<grid, 256>>>(target, source, nni, nnw);
    }
    // 2) Zt = (w0[:, :256] @ sfeat)^T
    {
        dim3 grid(MSRC / 128, CO / 128, B_SZ);
        zt_kernel<<<grid, 256>>>(w0, sfeat, Zt);
    }
    // 3) weight splits (fp16 hi/lo)
    split_w_kernel<<<(CO * C1 + 255) / 256, 256>>>(w0, CIN, C2, C1, W0h, W0l);
    split_w_kernel<<<(CO * CO + 255) / 256, 256>>>(w1, CO, 0, CO, W1h, W1l);
    // 4) tfeat transpose -> fp16
    {
        dim3 grid(NPTS / 32, C1 / 32, B_SZ);
        tfeat_t_kernel<<<grid, 256>>>(tfeat, T);
    }
    // 5) layer 0: (W0h+W0l) @ T^T + gather(Zt) + BN + ReLU -> Y0^T fp16
    {
        dim3 grid(NPTS / 128, CO / 128, B_SZ);
        mma_layer_kernel<C1, true><<<grid, 256, SMEM_L0>>>(
            W0h, W0l, T, nullptr, Y0, g0, b0, mu0, var0, nni, nnw, Zt);
    }
    // 6) layer 1: (W1h+W1l) @ Y0^T + BN + ReLU -> out (B, CO, N) fp32
    {
        dim3 grid(NPTS / 128, CO / 128, B_SZ);
        mma_layer_kernel<CO, false><<<grid, 256, SMEM_L1>>>(
            W1h, W1l, Y0, out, nullptr, g1, b1, mu1, var1, nullptr, nullptr, nullptr);
    }
    (void)in_sizes; (void)n_in; (void)out_size;
}

// round 7
// speedup vs baseline: 3.5194x; 1.0048x over previous
#include <cuda_runtime.h>
#include <cuda_fp16.h>
#include <cstdint>

#define B_SZ 8
#define NPTS 16384
#define MSRC 1024
#define C1   128
#define C2   256
#define CIN  384
#define CO   256
#define BN_EPS 1e-5f

// ---------------------------------------------------------------------------
// Scratch (allocation-free)
// ---------------------------------------------------------------------------
__device__ __align__(256) float  g_Zt [(size_t)B_SZ * MSRC * CO];
__device__ __align__(256) int4   g_nni[(size_t)B_SZ * NPTS];
__device__ __align__(256) float4 g_nnw[(size_t)B_SZ * NPTS];
__device__ __align__(256) __half g_W0h[CO * C1], g_W0l[CO * C1];
__device__ __align__(256) __half g_W1h[CO * CO], g_W1l[CO * CO];
__device__ __align__(256) __half g_T  [(size_t)B_SZ * NPTS * C1];   // tfeat^T fp16
__device__ __align__(256) __half g_Y0 [(size_t)B_SZ * NPTS * CO];   // Y0^T fp16

// ---------------------------------------------------------------------------
// PTX helpers (sm_100-safe)
// ---------------------------------------------------------------------------
__device__ __forceinline__ uint32_t smem_u32(const void* p) {
    uint32_t a;
    asm("{ .reg .u64 t; cvta.to.shared.u64 t, %1; cvt.u32.u64 %0, t; }" : "=r"(a) : "l"(p));
    return a;
}
#define CP16(dst, src) \
    asm volatile("cp.async.cg.shared.global [%0], [%1], 16;" :: "r"(dst), "l"(src))
#define CP_COMMIT() asm volatile("cp.async.commit_group;" ::: "memory")
#define CP_WAIT(n)  asm volatile("cp.async.wait_group %0;" :: "n"(n) : "memory")

#define LDSM4(r, addr) \
    asm volatile("ldmatrix.sync.aligned.m8n8.x4.shared.b16 {%0,%1,%2,%3}, [%4];" \
        : "=r"((r)[0]), "=r"((r)[1]), "=r"((r)[2]), "=r"((r)[3]) : "r"(addr))

#define MMA_F16(d, a, b0, b1) \
    asm volatile("mma.sync.aligned.m16n8k16.row.col.f32.f16.f16.f32 " \
        "{%0,%1,%2,%3}, {%4,%5,%6,%7}, {%8,%9}, {%0,%1,%2,%3};" \
        : "+f"((d)[0]), "+f"((d)[1]), "+f"((d)[2]), "+f"((d)[3]) \
        : "r"((a)[0]), "r"((a)[1]), "r"((a)[2]), "r"((a)[3]), "r"(b0), "r"(b1))

// ---------------------------------------------------------------------------
// three_nn (unchanged)
// ---------------------------------------------------------------------------
__global__ void __launch_bounds__(256)
three_nn_kernel(const float* __restrict__ target, const float* __restrict__ source,
                int4* __restrict__ nni, float4* __restrict__ nnw)
{
    const int b = blockIdx.y, t = threadIdx.x;
    const int i = blockIdx.x * 256 + t;
    __shared__ float4 s[MSRC];
    const float* src = source + (size_t)b * MSRC * 3;
    for (int j = t; j < MSRC; j += 256) {
        const float x = src[j * 3 + 0], y = src[j * 3 + 1], z = src[j * 3 + 2];
        s[j] = make_float4(x, y, z, x * x + y * y + z * z);
    }
    __syncthreads();
    const float* tp = target + ((size_t)b * NPTS + i) * 3;
    const float px = tp[0], py = tp[1], pz = tp[2];
    const float qx = -2.0f * px, qy = -2.0f * py, qz = -2.0f * pz;
    float e0 = 3.4e38f, e1 = 3.4e38f, e2 = 3.4e38f;
    int   j0 = 0, j1 = 0, j2 = 0;
    #pragma unroll 8
    for (int j = 0; j < MSRC; j++) {
        const float4 v = s[j];
        const float e = fmaf(qx, v.x, fmaf(qy, v.y, fmaf(qz, v.z, v.w)));
        if (e < e0)      { e2 = e1; j2 = j1; e1 = e0; j1 = j0; e0 = e; j0 = j; }
        else if (e < e1) { e2 = e1; j2 = j1; e1 = e;  j1 = j; }
        else if (e < e2) { e2 = e;  j2 = j; }
    }
    float d[3]; int jj[3] = {j0, j1, j2};
    #pragma unroll
    for (int k = 0; k < 3; k++) {
        const float4 v = s[jj[k]];
        const float dx = px - v.x, dy = py - v.y, dz = pz - v.z;
        d[k] = dx * dx + dy * dy + dz * dz;
    }
    const float r0 = 1.0f / (d[0] + 1e-8f), r1 = 1.0f / (d[1] + 1e-8f), r2 = 1.0f / (d[2] + 1e-8f);
    const float rs = 1.0f / (r0 + r1 + r2);
    nni[(size_t)b * NPTS + i] = make_int4(j0, j1, j2, 0);
    nnw[(size_t)b * NPTS + i] = make_float4(r0 * rs, r1 * rs, r2 * rs, 0.0f);
}

// ---------------------------------------------------------------------------
// Zt = (w0[:, :256] @ sfeat)^T per batch (fp32, unchanged)
// ---------------------------------------------------------------------------
__global__ void __launch_bounds__(256, 2)
zt_kernel(const float* __restrict__ w0, const float* __restrict__ sfeat, float* __restrict__ Zt)
{
    constexpr int BK = 16, TM = 8, TN = 8;
    __shared__ float Ss[BK][128];
    __shared__ float Ws[BK][128];
    const int b = blockIdx.z, J0 = blockIdx.x * 128, O0 = blockIdx.y * 128;
    const float* sf = sfeat + (size_t)b * C2 * MSRC;
    const int tid = threadIdx.x;
    const int rowO = tid >> 2, colK = (tid & 3) * 4;
    const int rowK = tid >> 5, colJ = (tid & 31) * 4;
    const int tj = (tid >> 4) * TM, to = (tid & 15) * TN;
    float acc[TM][TN];
    #pragma unroll
    for (int i = 0; i < TM; i++)
        #pragma unroll
        for (int j = 0; j < TN; j++) acc[i][j] = 0.0f;
    for (int k0 = 0; k0 < C2; k0 += BK) {
        #pragma unroll
        for (int p = 0; p < 2; p++) {
            const int r = rowO + p * 64;
            const float4 v = *(const float4*)(w0 + (size_t)(O0 + r) * CIN + k0 + colK);
            Ws[colK + 0][r] = v.x; Ws[colK + 1][r] = v.y;
            Ws[colK + 2][r] = v.z; Ws[colK + 3][r] = v.w;
        }
        #pragma unroll
        for (int p = 0; p < 2; p++) {
            const int r = rowK + p * 8;
            *(float4*)&Ss[r][colJ] = *(const float4*)(sf + (size_t)(k0 + r) * MSRC + J0 + colJ);
        }
        __syncthreads();
        #pragma unroll
        for (int kk = 0; kk < BK; kk++) {
            float a[TM], w[TN];
            #pragma unroll
            for (int i = 0; i < TM; i += 4) *(float4*)&a[i] = *(const float4*)&Ss[kk][tj + i];
            #pragma unroll
            for (int j = 0; j < TN; j += 4) *(float4*)&w[j] = *(const float4*)&Ws[kk][to + j];
            #pragma unroll
            for (int i = 0; i < TM; i++)
                #pragma unroll
                for (int j = 0; j < TN; j++) acc[i][j] = fmaf(a[i], w[j], acc[i][j]);
        }
        __syncthreads();
    }
    float* Zb = Zt + (size_t)b * MSRC * CO;
    #pragma unroll
    for (int i = 0; i < TM; i++)
        #pragma unroll
        for (int j = 0; j < TN; j += 4) {
            float4 v = make_float4(acc[i][j], acc[i][j+1], acc[i][j+2], acc[i][j+3]);
            *(float4*)(Zb + (size_t)(J0 + tj + i) * CO + O0 + to + j) = v;
        }
}

// ---------------------------------------------------------------------------
// Weight hi/lo split (fp16 planes)
// ---------------------------------------------------------------------------
__global__ void split_w_kernel(const float* __restrict__ w, int lda, int c0, int KW,
                               __half* __restrict__ Wh, __half* __restrict__ Wl)
{
    const int idx = blockIdx.x * 256 + threadIdx.x;
    if (idx >= CO * KW) return;
    const int o = idx / KW, k = idx % KW;
    const float x = w[(size_t)o * lda + c0 + k];
    const __half h = __float2half_rn(x);
    Wh[idx] = h;
    Wl[idx] = __float2half_rn(x - __half2float(h));
}

// ---------------------------------------------------------------------------
// tfeat transpose: (B,C1,N) fp32 -> (B,N,C1) fp16
// ---------------------------------------------------------------------------
__global__ void __launch_bounds__(256)
tfeat_t_kernel(const float* __restrict__ tfeat, __half* __restrict__ T)
{
    __shared__ float sm[32][33];
    const int b = blockIdx.z;
    const int n0 = blockIdx.x * 32, c0 = blockIdx.y * 32;
    const int tx = threadIdx.x & 31, ty = threadIdx.x >> 5;
    const float* src = tfeat + (size_t)b * C1 * NPTS;
    #pragma unroll
    for (int i = 0; i < 4; i++) {
        const int c = ty + i * 8;
        sm[c][tx] = src[(size_t)(c0 + c) * NPTS + n0 + tx];
    }
    __syncthreads();
    #pragma unroll
    for (int i = 0; i < 4; i++) {
        const int n = ty + i * 8;
        T[((size_t)b * NPTS + n0 + n) * C1 + c0 + tx] = __float2half_rn(sm[tx][n]);
    }
}

// ---------------------------------------------------------------------------
// fp16 2-pass mma.sync GEMM + fused epilogue.
// D[o][n] = sum_k (Wh+Wl)[o,k] * X^T[n,k].  CTA tile 128m x 128n, BK=32,
// 8 warps (4m x 2n), double-buffered cp.async, 2 CTAs/SM.
// ---------------------------------------------------------------------------
template<int KW, bool L0GATHER>
__global__ void __launch_bounds__(256, 2)
mma_layer_kernel(const __half* __restrict__ Wh, const __half* __restrict__ Wl,
                 const __half* __restrict__ X,
                 float* __restrict__ outF, __half* __restrict__ outH,
                 const float* __restrict__ gam, const float* __restrict__ bet,
                 const float* __restrict__ mu,  const float* __restrict__ var,
                 const int4* __restrict__ nni, const float4* __restrict__ nnw,
                 const float* __restrict__ Zt)
{
    constexpr int KC  = KW / 32;
    constexpr int TS  = 128 * 80;     // bytes per tile (row stride 40 halves = 80 B)
    constexpr int BUF = 3 * TS;       // Ah, Al, B
    extern __shared__ __align__(16) char smem[];
    const uint32_t sb = smem_u32(smem);

    const int tid = threadIdx.x, lane = tid & 31, wid = tid >> 5;
    const int wm = wid >> 1, wn = wid & 1;
    const int b = blockIdx.z, n0 = blockIdx.x * 128, m0 = blockIdx.y * 128;

    const __half* Ah_g = Wh + (size_t)m0 * KW;
    const __half* Al_g = Wl + (size_t)m0 * KW;
    const __half* B_g  = X  + ((size_t)b * NPTS + n0) * KW;

    const int lr = tid >> 2;         // row 0..63, +64 per iter
    const int lc = (tid & 3) * 8;    // k offset in halves: 0,8,16,24

    float acc[2][8][4];
    #pragma unroll
    for (int i = 0; i < 2; i++)
        #pragma unroll
        for (int j = 0; j < 8; j++)
            #pragma unroll
            for (int q = 0; q < 4; q++) acc[i][j][q] = 0.0f;

    // prologue: chunk 0 -> buffer 0
    #pragma unroll
    for (int it = 0; it < 2; it++) {
        const int r = lr + it * 64;
        const uint32_t so = (uint32_t)(r * 80 + lc * 2);
        CP16(sb + so,          Ah_g + (size_t)r * KW + lc);
        CP16(sb + TS + so,     Al_g + (size_t)r * KW + lc);
        CP16(sb + 2*TS + so,   B_g  + (size_t)r * KW + lc);
    }
    CP_COMMIT();

    for (int c = 0; c < KC; c++) {
        if (c + 1 < KC) {
            const int k0 = (c + 1) * 32;
            const uint32_t bufo = (uint32_t)(((c + 1) & 1) * BUF);
            #pragma unroll
            for (int it = 0; it < 2; it++) {
                const int r = lr + it * 64;
                const uint32_t so = bufo + (uint32_t)(r * 80 + lc * 2);
                CP16(sb + so,          Ah_g + (size_t)r * KW + k0 + lc);
                CP16(sb + TS + so,     Al_g + (size_t)r * KW + k0 + lc);
                CP16(sb + 2*TS + so,   B_g  + (size_t)r * KW + k0 + lc);
            }
            CP_COMMIT();
            CP_WAIT(1);
        } else {
            CP_WAIT(0);
        }
        __syncthreads();

        const uint32_t base = sb + (uint32_t)((c & 1) * BUF);
        #pragma unroll
        for (int kk = 0; kk < 2; kk++) {
            uint32_t ah[2][4], al[2][4];
            #pragma unroll
            for (int mt = 0; mt < 2; mt++) {
                const uint32_t ad = base
                    + (uint32_t)((wm * 32 + mt * 16 + (lane & 15)) * 80
                                 + (kk * 16 + ((lane >> 4) << 3)) * 2);
                LDSM4(ah[mt], ad);
                LDSM4(al[mt], ad + TS);
            }
            #pragma unroll
            for (int ng = 0; ng < 4; ng++) {
                uint32_t bh[4];
                const uint32_t bd = base + 2 * TS
                    + (uint32_t)((wn * 64 + ng * 16 + (lane & 7) + ((lane >> 4) << 3)) * 80
                                 + (kk * 16 + (((lane >> 3) & 1) << 3)) * 2);
                LDSM4(bh, bd);
                #pragma unroll
                for (int mt = 0; mt < 2; mt++) {
                    #pragma unroll
                    for (int hh = 0; hh < 2; hh++) {
                        float* d = acc[mt][ng * 2 + hh];
                        MMA_F16(d, ah[mt], bh[2 * hh], bh[2 * hh + 1]);
                        MMA_F16(d, al[mt], bh[2 * hh], bh[2 * hh + 1]);
                    }
                }
            }
        }
        __syncthreads();
    }

    // ---------------- Epilogue ----------------
    if (!L0GATHER) {
        #pragma unroll
        for (int mt = 0; mt < 2; mt++) {
            const int o0 = m0 + wm * 32 + mt * 16 + (lane >> 2);
            const float s0 = gam[o0] * rsqrtf(var[o0] + BN_EPS);
            const float c0 = bet[o0] - mu[o0] * s0;
            const int o1 = o0 + 8;
            const float s1 = gam[o1] * rsqrtf(var[o1] + BN_EPS);
            const float c1 = bet[o1] - mu[o1] * s1;
            #pragma unroll
            for (int j = 0; j < 8; j++) {
                const int n = n0 + wn * 64 + j * 8 + (lane & 3) * 2;
                float2 v0, v1;
                v0.x = fmaxf(fmaf(acc[mt][j][0], s0, c0), 0.0f);
                v0.y = fmaxf(fmaf(acc[mt][j][1], s0, c0), 0.0f);
                v1.x = fmaxf(fmaf(acc[mt][j][2], s1, c1), 0.0f);
                v1.y = fmaxf(fmaf(acc[mt][j][3], s1, c1), 0.0f);
                *(float2*)(outF + ((size_t)b * CO + o0) * NPTS + n) = v0;
                *(float2*)(outF + ((size_t)b * CO + o1) * NPTS + n) = v1;
            }
        }
    } else {
        // Bounce accumulators to smem as S[n][o] fp32 (stride 132)
        float* S = (float*)smem;
        #pragma unroll
        for (int mt = 0; mt < 2; mt++) {
            const int ol = wm * 32 + mt * 16 + (lane >> 2);
            #pragma unroll
            for (int j = 0; j < 8; j++) {
                const int nl = wn * 64 + j * 8 + (lane & 3) * 2;
                S[(nl + 0) * 132 + ol]     = acc[mt][j][0];
                S[(nl + 1) * 132 + ol]     = acc[mt][j][1];
                S[(nl + 0) * 132 + ol + 8] = acc[mt][j][2];
                S[(nl + 1) * 132 + ol + 8] = acc[mt][j][3];
            }
        }
        __syncthreads();

        const size_t bn = (size_t)b * NPTS;
        const float* Zb = Zt + (size_t)b * MSRC * CO;
        #pragma unroll 2
        for (int it = 0; it < 16; it++) {
            const int item = tid + it * 256;
            const int nl = item >> 5, o4 = (item & 31) * 4;
            const int n = n0 + nl, o = m0 + o4;
            float4 v = *(float4*)(S + nl * 132 + o4);
            const int4   ji = nni[bn + n];
            const float4 jw = nnw[bn + n];
            const float4 z0 = *(const float4*)(Zb + (size_t)ji.x * CO + o);
            const float4 z1 = *(const float4*)(Zb + (size_t)ji.y * CO + o);
            const float4 z2 = *(const float4*)(Zb + (size_t)ji.z * CO + o);
            v.x += jw.x * z0.x + jw.y * z1.x + jw.z * z2.x;
            v.y += jw.x * z0.y + jw.y * z1.y + jw.z * z2.y;
            v.z += jw.x * z0.z + jw.y * z1.z + jw.z * z2.z;
            v.w += jw.x * z0.w + jw.y * z1.w + jw.z * z2.w;
            const float4 g4 = *(const float4*)(gam + o);
            const float4 b4 = *(const float4*)(bet + o);
            const float4 m4 = *(const float4*)(mu  + o);
            const float4 q4 = *(const float4*)(var + o);
            const float sx = g4.x * rsqrtf(q4.x + BN_EPS);
            const float sy = g4.y * rsqrtf(q4.y + BN_EPS);
            const float sz = g4.z * rsqrtf(q4.z + BN_EPS);
            const float sw = g4.w * rsqrtf(q4.w + BN_EPS);
            union { __half h[4]; uint2 u; } H;
            H.h[0] = __float2half_rn(fmaxf(fmaf(v.x, sx, b4.x - m4.x * sx), 0.0f));
            H.h[1] = __float2half_rn(fmaxf(fmaf(v.y, sy, b4.y - m4.y * sy), 0.0f));
            H.h[2] = __float2half_rn(fmaxf(fmaf(v.z, sz, b4.z - m4.z * sz), 0.0f));
            H.h[3] = __float2half_rn(fmaxf(fmaf(v.w, sw, b4.w - m4.w * sw), 0.0f));
            *(uint2*)(outH + (bn + n) * CO + o) = H.u;
        }
    }
}

// ---------------------------------------------------------------------------
extern "C" void kernel_launch(void* const* d_in, const int* in_sizes, int n_in,
                              void* d_out, int out_size)
{
    const float* target = (const float*)d_in[0];
    const float* source = (const float*)d_in[1];
    const float* tfeat  = (const float*)d_in[2];
    const float* sfeat  = (const float*)d_in[3];
    const float* w0     = (const float*)d_in[4];
    const float* g0     = (const float*)d_in[5];
    const float* b0     = (const float*)d_in[6];
    const float* mu0    = (const float*)d_in[7];
    const float* var0   = (const float*)d_in[8];
    const float* w1     = (const float*)d_in[9];
    const float* g1     = (const float*)d_in[10];
    const float* b1     = (const float*)d_in[11];
    const float* mu1    = (const float*)d_in[12];
    const float* var1   = (const float*)d_in[13];
    float* out = (float*)d_out;

    float*  Zt;  cudaGetSymbolAddress((void**)&Zt,  g_Zt);
    int4*   nni; cudaGetSymbolAddress((void**)&nni, g_nni);
    float4* nnw; cudaGetSymbolAddress((void**)&nnw, g_nnw);
    __half *W0h, *W0l, *W1h, *W1l, *T, *Y0;
    cudaGetSymbolAddress((void**)&W0h, g_W0h); cudaGetSymbolAddress((void**)&W0l, g_W0l);
    cudaGetSymbolAddress((void**)&W1h, g_W1h); cudaGetSymbolAddress((void**)&W1l, g_W1l);
    cudaGetSymbolAddress((void**)&T,   g_T);   cudaGetSymbolAddress((void**)&Y0,  g_Y0);

    constexpr int SMEM_L0 = 128 * 132 * 4;     // 67584 (bounce) > 61440 (mma bufs)
    constexpr int SMEM_L1 = 2 * 3 * 128 * 80;  // 61440
    cudaFuncSetAttribute(mma_layer_kernel<C1, true>,
                         cudaFuncAttributeMaxDynamicSharedMemorySize, SMEM_L0);
    cudaFuncSetAttribute(mma_layer_kernel<CO, false>,
                         cudaFuncAttributeMaxDynamicSharedMemorySize, SMEM_L1);

    // 1) three_nn
    {
        dim3 grid(NPTS / 256, B_SZ);
        three_nn_kernel<<<grid, 256>>>(target, source, nni, nnw);
    }
    // 2) Zt = (w0[:, :256] @ sfeat)^T
    {
        dim3 grid(MSRC / 128, CO / 128, B_SZ);
        zt_kernel<<<grid, 256>>>(w0, sfeat, Zt);
    }
    // 3) weight splits (fp16 hi/lo)
    split_w_kernel<<<(CO * C1 + 255) / 256, 256>>>(w0, CIN, C2, C1, W0h, W0l);
    split_w_kernel<<<(CO * CO + 255) / 256, 256>>>(w1, CO, 0, CO, W1h, W1l);
    // 4) tfeat transpose -> fp16
    {
        dim3 grid(NPTS / 32, C1 / 32, B_SZ);
        tfeat_t_kernel<<<grid, 256>>>(tfeat, T);
    }
    // 5) layer 0: (W0h+W0l) @ T^T + gather(Zt) + BN + ReLU -> Y0^T fp16
    {
        dim3 grid(NPTS / 128, CO / 128, B_SZ);
        mma_layer_kernel<C1, true><<<grid, 256, SMEM_L0>>>(
            W0h, W0l, T, nullptr, Y0, g0, b0, mu0, var0, nni, nnw, Zt);
    }
    // 6) layer 1: (W1h+W1l) @ Y0^T + BN + ReLU -> out (B, CO, N) fp32
    {
        dim3 grid(NPTS / 128, CO / 128, B_SZ);
        mma_layer_kernel<CO, false><<<grid, 256, SMEM_L1>>>(
            W1h, W1l, Y0, out, nullptr, g1, b1, mu1, var1, nullptr, nullptr, nullptr);
    }
    (void)in_sizes; (void)n_in; (void)out_size;
}

// round 8
// speedup vs baseline: 4.1288x; 1.1731x over previous
#include <cuda_runtime.h>
#include <cuda_fp16.h>
#include <cstdint>

#define B_SZ 8
#define NPTS 16384
#define MSRC 1024
#define C1   128
#define C2   256
#define CIN  384
#define CO   256
#define BN_EPS 1e-5f

// ---------------------------------------------------------------------------
// Scratch (allocation-free)
// ---------------------------------------------------------------------------
__device__ __align__(256) float  g_Zt [(size_t)B_SZ * MSRC * CO];
__device__ __align__(256) int4   g_nni[(size_t)B_SZ * NPTS];
__device__ __align__(256) float4 g_nnw[(size_t)B_SZ * NPTS];
__device__ __align__(256) __half g_W0 [CO * C1];
__device__ __align__(256) __half g_W1 [CO * CO];
__device__ __align__(256) __half g_T  [(size_t)B_SZ * NPTS * C1];   // tfeat^T fp16
__device__ __align__(256) __half g_Y0 [(size_t)B_SZ * NPTS * CO];   // Y0^T fp16

// ---------------------------------------------------------------------------
// PTX helpers (sm_100-safe)
// ---------------------------------------------------------------------------
__device__ __forceinline__ uint32_t smem_u32(const void* p) {
    uint32_t a;
    asm("{ .reg .u64 t; cvta.to.shared.u64 t, %1; cvt.u32.u64 %0, t; }" : "=r"(a) : "l"(p));
    return a;
}
#define CP16(dst, src) \
    asm volatile("cp.async.cg.shared.global [%0], [%1], 16;" :: "r"(dst), "l"(src))
#define CP_COMMIT() asm volatile("cp.async.commit_group;" ::: "memory")
#define CP_WAIT(n)  asm volatile("cp.async.wait_group %0;" :: "n"(n) : "memory")

#define LDSM4(r, addr) \
    asm volatile("ldmatrix.sync.aligned.m8n8.x4.shared.b16 {%0,%1,%2,%3}, [%4];" \
        : "=r"((r)[0]), "=r"((r)[1]), "=r"((r)[2]), "=r"((r)[3]) : "r"(addr))

#define MMA_F16(d, a, b0, b1) \
    asm volatile("mma.sync.aligned.m16n8k16.row.col.f32.f16.f16.f32 " \
        "{%0,%1,%2,%3}, {%4,%5,%6,%7}, {%8,%9}, {%0,%1,%2,%3};" \
        : "+f"((d)[0]), "+f"((d)[1]), "+f"((d)[2]), "+f"((d)[3]) \
        : "r"((a)[0]), "r"((a)[1]), "r"((a)[2]), "r"((a)[3]), "r"(b0), "r"(b1))

// ---------------------------------------------------------------------------
// three_nn (unchanged)
// ---------------------------------------------------------------------------
__global__ void __launch_bounds__(256)
three_nn_kernel(const float* __restrict__ target, const float* __restrict__ source,
                int4* __restrict__ nni, float4* __restrict__ nnw)
{
    const int b = blockIdx.y, t = threadIdx.x;
    const int i = blockIdx.x * 256 + t;
    __shared__ float4 s[MSRC];
    const float* src = source + (size_t)b * MSRC * 3;
    for (int j = t; j < MSRC; j += 256) {
        const float x = src[j * 3 + 0], y = src[j * 3 + 1], z = src[j * 3 + 2];
        s[j] = make_float4(x, y, z, x * x + y * y + z * z);
    }
    __syncthreads();
    const float* tp = target + ((size_t)b * NPTS + i) * 3;
    const float px = tp[0], py = tp[1], pz = tp[2];
    const float qx = -2.0f * px, qy = -2.0f * py, qz = -2.0f * pz;
    float e0 = 3.4e38f, e1 = 3.4e38f, e2 = 3.4e38f;
    int   j0 = 0, j1 = 0, j2 = 0;
    #pragma unroll 8
    for (int j = 0; j < MSRC; j++) {
        const float4 v = s[j];
        const float e = fmaf(qx, v.x, fmaf(qy, v.y, fmaf(qz, v.z, v.w)));
        if (e < e0)      { e2 = e1; j2 = j1; e1 = e0; j1 = j0; e0 = e; j0 = j; }
        else if (e < e1) { e2 = e1; j2 = j1; e1 = e;  j1 = j; }
        else if (e < e2) { e2 = e;  j2 = j; }
    }
    float d[3]; int jj[3] = {j0, j1, j2};
    #pragma unroll
    for (int k = 0; k < 3; k++) {
        const float4 v = s[jj[k]];
        const float dx = px - v.x, dy = py - v.y, dz = pz - v.z;
        d[k] = dx * dx + dy * dy + dz * dz;
    }
    const float r0 = 1.0f / (d[0] + 1e-8f), r1 = 1.0f / (d[1] + 1e-8f), r2 = 1.0f / (d[2] + 1e-8f);
    const float rs = 1.0f / (r0 + r1 + r2);
    nni[(size_t)b * NPTS + i] = make_int4(j0, j1, j2, 0);
    nnw[(size_t)b * NPTS + i] = make_float4(r0 * rs, r1 * rs, r2 * rs, 0.0f);
}

// ---------------------------------------------------------------------------
// Zt = (w0[:, :256] @ sfeat)^T per batch (fp32, unchanged — keeps interp exact)
// ---------------------------------------------------------------------------
__global__ void __launch_bounds__(256, 2)
zt_kernel(const float* __restrict__ w0, const float* __restrict__ sfeat, float* __restrict__ Zt)
{
    constexpr int BK = 16, TM = 8, TN = 8;
    __shared__ float Ss[BK][128];
    __shared__ float Ws[BK][128];
    const int b = blockIdx.z, J0 = blockIdx.x * 128, O0 = blockIdx.y * 128;
    const float* sf = sfeat + (size_t)b * C2 * MSRC;
    const int tid = threadIdx.x;
    const int rowO = tid >> 2, colK = (tid & 3) * 4;
    const int rowK = tid >> 5, colJ = (tid & 31) * 4;
    const int tj = (tid >> 4) * TM, to = (tid & 15) * TN;
    float acc[TM][TN];
    #pragma unroll
    for (int i = 0; i < TM; i++)
        #pragma unroll
        for (int j = 0; j < TN; j++) acc[i][j] = 0.0f;
    for (int k0 = 0; k0 < C2; k0 += BK) {
        #pragma unroll
        for (int p = 0; p < 2; p++) {
            const int r = rowO + p * 64;
            const float4 v = *(const float4*)(w0 + (size_t)(O0 + r) * CIN + k0 + colK);
            Ws[colK + 0][r] = v.x; Ws[colK + 1][r] = v.y;
            Ws[colK + 2][r] = v.z; Ws[colK + 3][r] = v.w;
        }
        #pragma unroll
        for (int p = 0; p < 2; p++) {
            const int r = rowK + p * 8;
            *(float4*)&Ss[r][colJ] = *(const float4*)(sf + (size_t)(k0 + r) * MSRC + J0 + colJ);
        }
        __syncthreads();
        #pragma unroll
        for (int kk = 0; kk < BK; kk++) {
            float a[TM], w[TN];
            #pragma unroll
            for (int i = 0; i < TM; i += 4) *(float4*)&a[i] = *(const float4*)&Ss[kk][tj + i];
            #pragma unroll
            for (int j = 0; j < TN; j += 4) *(float4*)&w[j] = *(const float4*)&Ws[kk][to + j];
            #pragma unroll
            for (int i = 0; i < TM; i++)
                #pragma unroll
                for (int j = 0; j < TN; j++) acc[i][j] = fmaf(a[i], w[j], acc[i][j]);
        }
        __syncthreads();
    }
    float* Zb = Zt + (size_t)b * MSRC * CO;
    #pragma unroll
    for (int i = 0; i < TM; i++)
        #pragma unroll
        for (int j = 0; j < TN; j += 4) {
            float4 v = make_float4(acc[i][j], acc[i][j+1], acc[i][j+2], acc[i][j+3]);
            *(float4*)(Zb + (size_t)(J0 + tj + i) * CO + O0 + to + j) = v;
        }
}

// ---------------------------------------------------------------------------
// Weight convert (single fp16 plane)
// ---------------------------------------------------------------------------
__global__ void conv_w_kernel(const float* __restrict__ w, int lda, int c0, int KW,
                              __half* __restrict__ W)
{
    const int idx = blockIdx.x * 256 + threadIdx.x;
    if (idx >= CO * KW) return;
    const int o = idx / KW, k = idx % KW;
    W[idx] = __float2half_rn(w[(size_t)o * lda + c0 + k]);
}

// ---------------------------------------------------------------------------
// tfeat transpose: (B,C1,N) fp32 -> (B,N,C1) fp16
// ---------------------------------------------------------------------------
__global__ void __launch_bounds__(256)
tfeat_t_kernel(const float* __restrict__ tfeat, __half* __restrict__ T)
{
    __shared__ float sm[32][33];
    const int b = blockIdx.z;
    const int n0 = blockIdx.x * 32, c0 = blockIdx.y * 32;
    const int tx = threadIdx.x & 31, ty = threadIdx.x >> 5;
    const float* src = tfeat + (size_t)b * C1 * NPTS;
    #pragma unroll
    for (int i = 0; i < 4; i++) {
        const int c = ty + i * 8;
        sm[c][tx] = src[(size_t)(c0 + c) * NPTS + n0 + tx];
    }
    __syncthreads();
    #pragma unroll
    for (int i = 0; i < 4; i++) {
        const int n = ty + i * 8;
        T[((size_t)b * NPTS + n0 + n) * C1 + c0 + tx] = __float2half_rn(sm[tx][n]);
    }
}

// ---------------------------------------------------------------------------
// fp16 single-pass mma.sync GEMM + fused epilogue.
// D[o][n] = sum_k W[o,k] * X^T[n,k].  CTA tile 128m x 128n, BK=64,
// 8 warps (4m x 2n), double-buffered cp.async, 2 CTAs/SM.
// ---------------------------------------------------------------------------
template<int KW, bool L0GATHER>
__global__ void __launch_bounds__(256, 2)
mma_layer_kernel(const __half* __restrict__ W, const __half* __restrict__ X,
                 float* __restrict__ outF, __half* __restrict__ outH,
                 const float* __restrict__ gam, const float* __restrict__ bet,
                 const float* __restrict__ mu,  const float* __restrict__ var,
                 const int4* __restrict__ nni, const float4* __restrict__ nnw,
                 const float* __restrict__ Zt)
{
    constexpr int KC  = KW / 64;
    constexpr int TS  = 128 * 144;    // bytes per tile (row stride 72 halves = 144 B)
    constexpr int BUF = 2 * TS;       // A, B
    extern __shared__ __align__(16) char smem[];
    const uint32_t sb = smem_u32(smem);

    const int tid = threadIdx.x, lane = tid & 31, wid = tid >> 5;
    const int wm = wid >> 1, wn = wid & 1;
    const int b = blockIdx.z, n0 = blockIdx.x * 128, m0 = blockIdx.y * 128;

    const __half* A_g = W + (size_t)m0 * KW;
    const __half* B_g = X + ((size_t)b * NPTS + n0) * KW;

    const int lr = tid >> 3;         // row 0..31, +32 per iter
    const int lc = (tid & 7) * 8;    // k offset in halves: 0..56

    float acc[2][8][4];
    #pragma unroll
    for (int i = 0; i < 2; i++)
        #pragma unroll
        for (int j = 0; j < 8; j++)
            #pragma unroll
            for (int q = 0; q < 4; q++) acc[i][j][q] = 0.0f;

    // prologue: chunk 0 -> buffer 0
    #pragma unroll
    for (int it = 0; it < 4; it++) {
        const int r = lr + it * 32;
        const uint32_t so = (uint32_t)(r * 144 + lc * 2);
        CP16(sb + so,      A_g + (size_t)r * KW + lc);
        CP16(sb + TS + so, B_g + (size_t)r * KW + lc);
    }
    CP_COMMIT();

    for (int c = 0; c < KC; c++) {
        if (c + 1 < KC) {
            const int k0 = (c + 1) * 64;
            const uint32_t bufo = (uint32_t)(((c + 1) & 1) * BUF);
            #pragma unroll
            for (int it = 0; it < 4; it++) {
                const int r = lr + it * 32;
                const uint32_t so = bufo + (uint32_t)(r * 144 + lc * 2);
                CP16(sb + so,      A_g + (size_t)r * KW + k0 + lc);
                CP16(sb + TS + so, B_g + (size_t)r * KW + k0 + lc);
            }
            CP_COMMIT();
            CP_WAIT(1);
        } else {
            CP_WAIT(0);
        }
        __syncthreads();

        const uint32_t base = sb + (uint32_t)((c & 1) * BUF);
        #pragma unroll
        for (int kk = 0; kk < 4; kk++) {
            uint32_t ah[2][4];
            #pragma unroll
            for (int mt = 0; mt < 2; mt++) {
                const uint32_t ad = base
                    + (uint32_t)((wm * 32 + mt * 16 + (lane & 15)) * 144
                                 + (kk * 16 + ((lane >> 4) << 3)) * 2);
                LDSM4(ah[mt], ad);
            }
            #pragma unroll
            for (int ng = 0; ng < 4; ng++) {
                uint32_t bh[4];
                const uint32_t bd = base + TS
                    + (uint32_t)((wn * 64 + ng * 16 + (lane & 7) + ((lane >> 4) << 3)) * 144
                                 + (kk * 16 + (((lane >> 3) & 1) << 3)) * 2);
                LDSM4(bh, bd);
                #pragma unroll
                for (int mt = 0; mt < 2; mt++) {
                    #pragma unroll
                    for (int hh = 0; hh < 2; hh++)
                        MMA_F16(acc[mt][ng * 2 + hh], ah[mt], bh[2 * hh], bh[2 * hh + 1]);
                }
            }
        }
        __syncthreads();
    }

    // ---------------- Epilogue ----------------
    if (!L0GATHER) {
        #pragma unroll
        for (int mt = 0; mt < 2; mt++) {
            const int o0 = m0 + wm * 32 + mt * 16 + (lane >> 2);
            const float s0 = gam[o0] * rsqrtf(var[o0] + BN_EPS);
            const float c0 = bet[o0] - mu[o0] * s0;
            const int o1 = o0 + 8;
            const float s1 = gam[o1] * rsqrtf(var[o1] + BN_EPS);
            const float c1 = bet[o1] - mu[o1] * s1;
            #pragma unroll
            for (int j = 0; j < 8; j++) {
                const int n = n0 + wn * 64 + j * 8 + (lane & 3) * 2;
                float2 v0, v1;
                v0.x = fmaxf(fmaf(acc[mt][j][0], s0, c0), 0.0f);
                v0.y = fmaxf(fmaf(acc[mt][j][1], s0, c0), 0.0f);
                v1.x = fmaxf(fmaf(acc[mt][j][2], s1, c1), 0.0f);
                v1.y = fmaxf(fmaf(acc[mt][j][3], s1, c1), 0.0f);
                *(float2*)(outF + ((size_t)b * CO + o0) * NPTS + n) = v0;
                *(float2*)(outF + ((size_t)b * CO + o1) * NPTS + n) = v1;
            }
        }
    } else {
        // Bounce accumulators to smem as S[n][o] fp32 (stride 132)
        float* S = (float*)smem;
        #pragma unroll
        for (int mt = 0; mt < 2; mt++) {
            const int ol = wm * 32 + mt * 16 + (lane >> 2);
            #pragma unroll
            for (int j = 0; j < 8; j++) {
                const int nl = wn * 64 + j * 8 + (lane & 3) * 2;
                S[(nl + 0) * 132 + ol]     = acc[mt][j][0];
                S[(nl + 1) * 132 + ol]     = acc[mt][j][1];
                S[(nl + 0) * 132 + ol + 8] = acc[mt][j][2];
                S[(nl + 1) * 132 + ol + 8] = acc[mt][j][3];
            }
        }
        __syncthreads();

        const size_t bn = (size_t)b * NPTS;
        const float* Zb = Zt + (size_t)b * MSRC * CO;
        #pragma unroll 2
        for (int it = 0; it < 16; it++) {
            const int item = tid + it * 256;
            const int nl = item >> 5, o4 = (item & 31) * 4;
            const int n = n0 + nl, o = m0 + o4;
            float4 v = *(float4*)(S + nl * 132 + o4);
            const int4   ji = nni[bn + n];
            const float4 jw = nnw[bn + n];
            const float4 z0 = *(const float4*)(Zb + (size_t)ji.x * CO + o);
            const float4 z1 = *(const float4*)(Zb + (size_t)ji.y * CO + o);
            const float4 z2 = *(const float4*)(Zb + (size_t)ji.z * CO + o);
            v.x += jw.x * z0.x + jw.y * z1.x + jw.z * z2.x;
            v.y += jw.x * z0.y + jw.y * z1.y + jw.z * z2.y;
            v.z += jw.x * z0.z + jw.y * z1.z + jw.z * z2.z;
            v.w += jw.x * z0.w + jw.y * z1.w + jw.z * z2.w;
            const float4 g4 = *(const float4*)(gam + o);
            const float4 b4 = *(const float4*)(bet + o);
            const float4 m4 = *(const float4*)(mu  + o);
            const float4 q4 = *(const float4*)(var + o);
            const float sx = g4.x * rsqrtf(q4.x + BN_EPS);
            const float sy = g4.y * rsqrtf(q4.y + BN_EPS);
            const float sz = g4.z * rsqrtf(q4.z + BN_EPS);
            const float sw = g4.w * rsqrtf(q4.w + BN_EPS);
            union { __half h[4]; uint2 u; } H;
            H.h[0] = __float2half_rn(fmaxf(fmaf(v.x, sx, b4.x - m4.x * sx), 0.0f));
            H.h[1] = __float2half_rn(fmaxf(fmaf(v.y, sy, b4.y - m4.y * sy), 0.0f));
            H.h[2] = __float2half_rn(fmaxf(fmaf(v.z, sz, b4.z - m4.z * sz), 0.0f));
            H.h[3] = __float2half_rn(fmaxf(fmaf(v.w, sw, b4.w - m4.w * sw), 0.0f));
            *(uint2*)(outH + (bn + n) * CO + o) = H.u;
        }
    }
}

// ---------------------------------------------------------------------------
extern "C" void kernel_launch(void* const* d_in, const int* in_sizes, int n_in,
                              void* d_out, int out_size)
{
    const float* target = (const float*)d_in[0];
    const float* source = (const float*)d_in[1];
    const float* tfeat  = (const float*)d_in[2];
    const float* sfeat  = (const float*)d_in[3];
    const float* w0     = (const float*)d_in[4];
    const float* g0     = (const float*)d_in[5];
    const float* b0     = (const float*)d_in[6];
    const float* mu0    = (const float*)d_in[7];
    const float* var0   = (const float*)d_in[8];
    const float* w1     = (const float*)d_in[9];
    const float* g1     = (const float*)d_in[10];
    const float* b1     = (const float*)d_in[11];
    const float* mu1    = (const float*)d_in[12];
    const float* var1   = (const float*)d_in[13];
    float* out = (float*)d_out;

    float*  Zt;  cudaGetSymbolAddress((void**)&Zt,  g_Zt);
    int4*   nni; cudaGetSymbolAddress((void**)&nni, g_nni);
    float4* nnw; cudaGetSymbolAddress((void**)&nnw, g_nnw);
    __half *W0, *W1, *T, *Y0;
    cudaGetSymbolAddress((void**)&W0, g_W0); cudaGetSymbolAddress((void**)&W1, g_W1);
    cudaGetSymbolAddress((void**)&T,  g_T);  cudaGetSymbolAddress((void**)&Y0, g_Y0);

    constexpr int SMEM_MMA = 2 * 2 * 128 * 144;  // 73728 B (>= 67584 bounce)
    cudaFuncSetAttribute(mma_layer_kernel<C1, true>,
                         cudaFuncAttributeMaxDynamicSharedMemorySize, SMEM_MMA);
    cudaFuncSetAttribute(mma_layer_kernel<CO, false>,
                         cudaFuncAttributeMaxDynamicSharedMemorySize, SMEM_MMA);

    // 1) three_nn
    {
        dim3 grid(NPTS / 256, B_SZ);
        three_nn_kernel<<<grid, 256>>>(target, source, nni, nnw);
    }
    // 2) Zt = (w0[:, :256] @ sfeat)^T  (fp32 — interp path stays exact)
    {
        dim3 grid(MSRC / 128, CO / 128, B_SZ);
        zt_kernel<<<grid, 256>>>(w0, sfeat, Zt);
    }
    // 3) weight converts (single fp16 plane)
    conv_w_kernel<<<(CO * C1 + 255) / 256, 256>>>(w0, CIN, C2, C1, W0);
    conv_w_kernel<<<(CO * CO + 255) / 256, 256>>>(w1, CO, 0, CO, W1);
    // 4) tfeat transpose -> fp16
    {
        dim3 grid(NPTS / 32, C1 / 32, B_SZ);
        tfeat_t_kernel<<<grid, 256>>>(tfeat, T);
    }
    // 5) layer 0: W0 @ T^T + gather(Zt) + BN + ReLU -> Y0^T fp16
    {
        dim3 grid(NPTS / 128, CO / 128, B_SZ);
        mma_layer_kernel<C1, true><<<grid, 256, SMEM_MMA>>>(
            W0, T, nullptr, Y0, g0, b0, mu0, var0, nni, nnw, Zt);
    }
    // 6) layer 1: W1 @ Y0^T + BN + ReLU -> out (B, CO, N) fp32
    {
        dim3 grid(NPTS / 128, CO / 128, B_SZ);
        mma_layer_kernel<CO, false><<<grid, 256, SMEM_MMA>>>(
            W1, Y0, out, nullptr, g1, b1, mu1, var1, nullptr, nullptr, nullptr);
    }
    (void)in_sizes; (void)n_in; (void)out_size;
}